// round 1
// baseline (speedup 1.0000x reference)
#include <cuda_runtime.h>
#include <math.h>

// ---------------- constants ----------------
#define NB 4
#define HW 2500
#define CIN 512
#define COUT 512
#define KDIM 4608          // 512*9
#define NANCH 22500
#define NPRE 3000
#define NPOST 300
#define NCHUNK 6
#define CHUNK 4096
#define PADN (NCHUNK*CHUNK)   // 24576

#define OFF_LOCS 0
#define SZ_LOCS (NB*NANCH*4)           // 360000
#define OFF_SCORES (OFF_LOCS+SZ_LOCS)  // 360000
#define SZ_SCORES (NB*NANCH*2)         // 180000
#define OFF_ROIS (OFF_SCORES+SZ_SCORES)// 540000
#define SZ_ROIS (NB*NPOST*4)           // 4800
#define OFF_RIDX (OFF_ROIS+SZ_ROIS)    // 544800
#define SZ_RIDX (NB*NPOST)             // 1200
#define OFF_ANCH (OFF_RIDX+SZ_RIDX)    // 546000

// ---------------- scratch (device globals; no allocation allowed) ----------------
__device__ float g_feat[NB*HW*COUT];                 // NHWC feature map
__device__ float g_boxes[NB*NANCH*4];                // decoded+clipped boxes
__device__ unsigned char g_valid[NB*NANCH];          // min-size validity
__device__ unsigned long long g_keys[NB*PADN];       // sort keys per chunk
__device__ float g_sboxes[NB*NPRE*4];                // top-3000 boxes in exact order
__device__ unsigned char g_svalid[NB*NPRE];          // validity of top-3000

// ---------------- kernel 1: 3x3 conv (implicit-GEMM SGEMM, fp32) ----------------
// M=512 couts, N=2500 px (pad 2560), K=4608. Tile 128x128x8, 256 threads, 8x8 micro.
#define BM 128
#define BN 128
#define KC 8

__global__ __launch_bounds__(256, 2)
void conv3x3_kernel(const float* __restrict__ X, const float* __restrict__ W,
                    const float* __restrict__ bias) {
    __shared__ float As[KC][BM];
    __shared__ float Bs[KC][BN];

    const int pn0 = blockIdx.x * BN;      // pixel tile base
    const int cm0 = blockIdx.y * BM;      // cout tile base
    const int b   = blockIdx.z;
    const int tid = threadIdx.x;
    const int tx  = tid & 15;             // 0..15 -> 8 px each
    const int ty  = tid >> 4;             // 0..15 -> 8 couts each

    const float* Xb = X + b * (CIN * HW);

    // A-load mapping: each thread loads float4 of W
    const int arow = tid >> 1;
    const int acol = (tid & 1) * 4;
    // B-load mapping: each thread loads 4 consecutive pixels of one k row
    const int kl = tid >> 5;              // 0..7
    const int pl = (tid & 31) * 4;        // 0..124

    // precompute pixel coords for the 4 B elements (constant across k-loop)
    int py[4], px[4];
#pragma unroll
    for (int q = 0; q < 4; q++) {
        int p = pn0 + pl + q;
        if (p < HW) { py[q] = p / 50; px[q] = p - py[q] * 50; }
        else        { py[q] = -1000;  px[q] = -1000; }
    }

    float acc[8][8];
#pragma unroll
    for (int i = 0; i < 8; i++)
#pragma unroll
        for (int j = 0; j < 8; j++) acc[i][j] = 0.f;

    for (int k0 = 0; k0 < KDIM; k0 += KC) {
        __syncthreads();
        // load A (weights): As[k][cout]
        float4 av = *(const float4*)(W + (size_t)(cm0 + arow) * KDIM + k0 + acol);
        As[acol + 0][arow] = av.x;
        As[acol + 1][arow] = av.y;
        As[acol + 2][arow] = av.z;
        As[acol + 3][arow] = av.w;
        // load B (im2col input)
        {
            int k = k0 + kl;
            int cin = k / 9, rem = k - cin * 9;
            int ky = rem / 3 - 1, kx = rem - (rem / 3) * 3 - 1;
            const float* Xc = Xb + cin * HW;
#pragma unroll
            for (int q = 0; q < 4; q++) {
                int yy = py[q] + ky, xx = px[q] + kx;
                float v = 0.f;
                if (yy >= 0 && yy < 50 && xx >= 0 && xx < 50) v = Xc[yy * 50 + xx];
                Bs[kl][pl + q] = v;
            }
        }
        __syncthreads();
#pragma unroll
        for (int kk = 0; kk < KC; kk++) {
            float a[8], bb[8];
            float4 a0 = *(float4*)&As[kk][ty * 8];
            float4 a1 = *(float4*)&As[kk][ty * 8 + 4];
            float4 b0 = *(float4*)&Bs[kk][tx * 8];
            float4 b1 = *(float4*)&Bs[kk][tx * 8 + 4];
            a[0]=a0.x; a[1]=a0.y; a[2]=a0.z; a[3]=a0.w;
            a[4]=a1.x; a[5]=a1.y; a[6]=a1.z; a[7]=a1.w;
            bb[0]=b0.x; bb[1]=b0.y; bb[2]=b0.z; bb[3]=b0.w;
            bb[4]=b1.x; bb[5]=b1.y; bb[6]=b1.z; bb[7]=b1.w;
#pragma unroll
            for (int i = 0; i < 8; i++)
#pragma unroll
                for (int j = 0; j < 8; j++)
                    acc[i][j] += a[i] * bb[j];
        }
    }

    // epilogue: bias + relu, store NHWC
    float bz[8];
#pragma unroll
    for (int i = 0; i < 8; i++) bz[i] = bias[cm0 + ty * 8 + i];

#pragma unroll
    for (int j = 0; j < 8; j++) {
        int p = pn0 + tx * 8 + j;
        if (p < HW) {
            float* dst = &g_feat[((size_t)(b * HW + p) << 9) + cm0 + ty * 8];
            float4 v0, v1;
            v0.x = fmaxf(acc[0][j] + bz[0], 0.f);
            v0.y = fmaxf(acc[1][j] + bz[1], 0.f);
            v0.z = fmaxf(acc[2][j] + bz[2], 0.f);
            v0.w = fmaxf(acc[3][j] + bz[3], 0.f);
            v1.x = fmaxf(acc[4][j] + bz[4], 0.f);
            v1.y = fmaxf(acc[5][j] + bz[5], 0.f);
            v1.z = fmaxf(acc[6][j] + bz[6], 0.f);
            v1.w = fmaxf(acc[7][j] + bz[7], 0.f);
            *(float4*)(dst)     = v0;
            *(float4*)(dst + 4) = v1;
        }
    }
}

// ---------------- kernel 2: 1x1 heads (loc 36ch + score 18ch) ----------------
__global__ __launch_bounds__(256)
void heads_kernel(const float* __restrict__ lw, const float* __restrict__ lb,
                  const float* __restrict__ sw, const float* __restrict__ sb,
                  float* __restrict__ out) {
    __shared__ float fs[8 * 512];
    const int b = blockIdx.y;
    const int p0 = blockIdx.x * 8;
    const int tid = threadIdx.x;

    for (int idx = tid * 4; idx < 8 * 512; idx += 256 * 4) {
        int pxi = idx >> 9;
        float4 v = make_float4(0.f, 0.f, 0.f, 0.f);
        if (p0 + pxi < HW)
            v = *(const float4*)&g_feat[((size_t)(b * HW + p0 + pxi) << 9) + (idx & 511)];
        *(float4*)&fs[idx] = v;
    }
    __syncthreads();

    for (int task = tid; task < 8 * 54; task += 256) {
        int pxi = task / 54;
        int o = task - pxi * 54;
        int p = p0 + pxi;
        if (p >= HW) continue;
        const float* wr = (o < 36) ? (lw + (o << 9)) : (sw + ((o - 36) << 9));
        const float* f = &fs[pxi << 9];
        float s = 0.f;
#pragma unroll 8
        for (int c = 0; c < 512; c += 4) {
            float4 wv = *(const float4*)&wr[c];
            float4 fv = *(const float4*)&f[c];
            s += wv.x * fv.x + wv.y * fv.y + wv.z * fv.z + wv.w * fv.w;
        }
        if (o < 36) {
            s += lb[o];
            int a = o >> 2, j = o & 3;
            out[OFF_LOCS + b * (NANCH * 4) + (p * 9 + a) * 4 + j] = s;
        } else {
            int oo = o - 36;
            s += sb[oo];
            int a = oo >> 1, j = oo & 1;
            out[OFF_SCORES + b * (NANCH * 2) + (p * 9 + a) * 2 + j] = s;
        }
    }
}

// ---------------- anchors (match numpy: base in double -> f32, shift add in f32) --
__device__ __forceinline__ void anchor_of(int i, float& ax1, float& ay1, float& ax2, float& ay2) {
    int p = i / 9, a = i - p * 9;
    int y = p / 50, x = p - y * 50;
    int ri = a / 3, si = a - ri * 3;
    const double ratios[3] = {0.5, 1.0, 2.0};
    const double scales[3] = {8.0, 16.0, 32.0};
    double hh = 16.0 * scales[si] * sqrt(ratios[ri]);
    double ww = 16.0 * scales[si] * sqrt(1.0 / ratios[ri]);
    float bx1 = (float)(8.0 - ww / 2.0);
    float by1 = (float)(8.0 - hh / 2.0);
    float bx2 = (float)(8.0 + ww / 2.0);
    float by2 = (float)(8.0 + hh / 2.0);
    float sx = (float)(x * 16);
    float sy = (float)(y * 16);
    ax1 = sx + bx1; ay1 = sy + by1; ax2 = sx + bx2; ay2 = sy + by2;
}

__global__ void anchor_kernel(float* __restrict__ out) {
    int i = blockIdx.x * blockDim.x + threadIdx.x;
    if (i >= NANCH) return;
    float a1, b1, a2, b2;
    anchor_of(i, a1, b1, a2, b2);
    out[OFF_ANCH + i * 4 + 0] = a1;
    out[OFF_ANCH + i * 4 + 1] = b1;
    out[OFF_ANCH + i * 4 + 2] = a2;
    out[OFF_ANCH + i * 4 + 3] = b2;
}

// ---------------- kernel 4: decode + clip + valid + sort keys ----------------
__device__ __forceinline__ float dim_to_float(const int* p) {
    int v = *p;
    if (v > 0 && v < 100000) return (float)v;
    return __int_as_float(v);   // in case the scalar arrived as float bits
}

__global__ void decode_kernel(const float* __restrict__ out,
                              const int* __restrict__ imh, const int* __restrict__ imw) {
    const int b = blockIdx.y;
    const int i = blockIdx.x * blockDim.x + threadIdx.x;
    if (i >= PADN) return;
    unsigned long long key;
    if (i < NANCH) {
        float ax1, ay1, ax2, ay2;
        anchor_of(i, ax1, ay1, ax2, ay2);
        const float* loc = out + OFF_LOCS + b * (NANCH * 4) + i * 4;
        float aw = ax2 - ax1, ah = ay2 - ay1;
        float acx = ax1 + 0.5f * aw, acy = ay1 + 0.5f * ah;
        float cx = loc[0] * aw + acx;
        float cy = loc[1] * ah + acy;
        float ww = expf(loc[2]) * aw;
        float hh = expf(loc[3]) * ah;
        float Wf = dim_to_float(imw), Hf = dim_to_float(imh);
        float x1 = fminf(fmaxf(cx - 0.5f * ww, 0.f), Wf);
        float y1 = fminf(fmaxf(cy - 0.5f * hh, 0.f), Hf);
        float x2 = fminf(fmaxf(cx + 0.5f * ww, 0.f), Wf);
        float y2 = fminf(fmaxf(cy + 0.5f * hh, 0.f), Hf);
        bool valid = (x2 - x1 + 1.f >= 16.f) && (y2 - y1 + 1.f >= 16.f);

        float* bx = &g_boxes[((size_t)b * NANCH + i) * 4];
        bx[0] = x1; bx[1] = y1; bx[2] = x2; bx[3] = y2;
        g_valid[b * NANCH + i] = valid ? 1 : 0;

        const float* sc = out + OFF_SCORES + b * (NANCH * 2) + i * 2;
        float s0 = sc[0], s1 = sc[1];
        float m = fmaxf(s0, s1);
        float e0 = expf(s0 - m), e1 = expf(s1 - m);
        float fg = e1 / (e0 + e1);
        float score = valid ? fg : __int_as_float(0xFF800000);  // -inf
        unsigned u = __float_as_uint(score);
        unsigned s = (u & 0x80000000u) ? ~u : (u | 0x80000000u); // ascending-sortable
        unsigned desc = ~s;                                      // descending score
        key = ((unsigned long long)desc << 32) | (unsigned)i;    // tiebreak: low idx first
    } else {
        key = 0xFFFFFFFFFFFFFFFFull;  // pad: sorts last
    }
    g_keys[(size_t)b * PADN + i] = key;
}

// ---------------- kernel 5: per-chunk bitonic sort (ascending key) ----------------
__global__ __launch_bounds__(512)
void sort_kernel() {
    __shared__ unsigned long long sk[CHUNK];
    const int c = blockIdx.x % NCHUNK;
    const int b = blockIdx.x / NCHUNK;
    unsigned long long* gk = g_keys + (size_t)b * PADN + c * CHUNK;
    for (int i = threadIdx.x; i < CHUNK; i += 512) sk[i] = gk[i];
    __syncthreads();
    for (int k = 2; k <= CHUNK; k <<= 1) {
        for (int j = k >> 1; j > 0; j >>= 1) {
            for (int t = threadIdx.x; t < CHUNK; t += 512) {
                int l = t ^ j;
                if (l > t) {
                    bool up = ((t & k) == 0);
                    unsigned long long a = sk[t], bv = sk[l];
                    if ((a > bv) == up) { sk[t] = bv; sk[l] = a; }
                }
            }
            __syncthreads();
        }
    }
    for (int i = threadIdx.x; i < CHUNK; i += 512) gk[i] = sk[i];
}

// ---------------- kernel 6: co-rank merge -> exact top-3000 in order ----------------
__global__ void merge_kernel() {
    const int b = blockIdx.y;
    const int t = blockIdx.x * blockDim.x + threadIdx.x;
    if (t >= NCHUNK * NPRE) return;
    const int c = t / NPRE;
    const int i = t - c * NPRE;
    const unsigned long long* base = g_keys + (size_t)b * PADN;
    unsigned long long key = base[c * CHUNK + i];
    if ((unsigned)(key >> 32) == 0xFFFFFFFFu) return;  // pad
    int rank = i;
#pragma unroll
    for (int cc = 0; cc < NCHUNK; cc++) {
        if (cc == c) continue;
        const unsigned long long* arr = base + cc * CHUNK;
        int pos = 0;
#pragma unroll
        for (int s = CHUNK / 2; s > 0; s >>= 1)
            if (arr[pos + s - 1] < key) pos += s;
        rank += pos;
    }
    if (rank < NPRE) {
        int idx = (int)(key & 0xFFFFFFFFull);
        int o = b * NPRE + rank;
        const float* src = &g_boxes[((size_t)b * NANCH + idx) * 4];
        float4 v = *(const float4*)src;
        ((float4*)g_sboxes)[o] = v;
        g_svalid[o] = g_valid[b * NANCH + idx];
    }
}

// ---------------- kernel 7: greedy NMS + output assembly ----------------
__global__ __launch_bounds__(1024)
void nms_kernel(float* __restrict__ out) {
    const int b = blockIdx.x;
    const int tid = threadIdx.x;
    __shared__ float4 box[NPRE];          // 48000 B
    __shared__ unsigned mk[(NPRE + 31) / 32]; // 94 words

    for (int i = tid; i < NPRE; i += 1024)
        box[i] = ((const float4*)g_sboxes)[b * NPRE + i];
    for (int w = tid; w < (NPRE + 31) / 32; w += 1024) {
        unsigned m = 0;
        for (int q = 0; q < 32; q++) {
            int j = w * 32 + q;
            if (j < NPRE && g_svalid[b * NPRE + j]) m |= (1u << q);
        }
        mk[w] = m;
    }
    __syncthreads();

    for (int i = 0; i < NPRE - 1; i++) {
        bool keep = (mk[i >> 5] >> (i & 31)) & 1;
        if (keep) {
            float4 bi = box[i];
            float ai = (bi.z - bi.x) * (bi.w - bi.y);
            for (int j = i + 1 + tid; j < NPRE; j += 1024) {
                float4 bj = box[j];
                float iw = fminf(bi.z, bj.z) - fmaxf(bi.x, bj.x);
                float ih = fminf(bi.w, bj.w) - fmaxf(bi.y, bj.y);
                iw = fmaxf(iw, 0.f); ih = fmaxf(ih, 0.f);
                float inter = iw * ih;
                float aj = (bj.z - bj.x) * (bj.w - bj.y);
                float iou = inter / (ai + aj - inter + 1e-9f);
                if (iou > 0.7f) atomicAnd(&mk[j >> 5], ~(1u << (j & 31)));
            }
        }
        __syncthreads();
    }

    // zero rois region, write roi_indices
    for (int q = tid; q < NPOST * 4; q += 1024) out[OFF_ROIS + b * (NPOST * 4) + q] = 0.f;
    for (int q = tid; q < NPOST; q += 1024) out[OFF_RIDX + b * NPOST + q] = (float)b;
    __syncthreads();

    // ordered compaction by warp 0 (stable argsort: kept boxes in rank order)
    if (tid < 32) {
        int cnt = 0;
        for (int w0 = 0; w0 < (NPRE + 31) / 32; w0++) {
            unsigned flags = mk[w0];
            int j = w0 * 32 + tid;
            bool f = (flags >> tid) & 1;
            int pos = cnt + __popc(flags & ((1u << tid) - 1u));
            if (f && pos < NPOST) {
                float4 bb = box[j];
                float* o = out + OFF_ROIS + b * (NPOST * 4) + pos * 4;
                o[0] = bb.x; o[1] = bb.y; o[2] = bb.z; o[3] = bb.w;
            }
            cnt += __popc(flags);
            if (cnt >= NPOST) break;
        }
    }
}

// ---------------- launcher ----------------
extern "C" void kernel_launch(void* const* d_in, const int* in_sizes, int n_in,
                              void* d_out, int out_size) {
    const float* x  = (const float*)d_in[0];
    const float* w1 = (const float*)d_in[1];
    const float* b1 = (const float*)d_in[2];
    const float* lw = (const float*)d_in[3];
    const float* lb = (const float*)d_in[4];
    const float* sw = (const float*)d_in[5];
    const float* sb = (const float*)d_in[6];
    const int* ih   = (const int*)d_in[7];
    const int* iw   = (const int*)d_in[8];
    float* out = (float*)d_out;

    conv3x3_kernel<<<dim3((HW + BN - 1) / BN, COUT / BM, NB), 256>>>(x, w1, b1);
    heads_kernel<<<dim3((HW + 7) / 8, NB), 256>>>(lw, lb, sw, sb, out);
    anchor_kernel<<<(NANCH + 255) / 256, 256>>>(out);
    decode_kernel<<<dim3((PADN + 255) / 256, NB), 256>>>(out, ih, iw);
    sort_kernel<<<NB * NCHUNK, 512>>>();
    merge_kernel<<<dim3((NCHUNK * NPRE + 255) / 256, NB), 256>>>();
    nms_kernel<<<NB, 1024>>>(out);
}

// round 2
// speedup vs baseline: 1.0011x; 1.0011x over previous
#include <cuda_runtime.h>
#include <math.h>

// ---------------- constants ----------------
#define NB 4
#define HW 2500
#define CIN 512
#define COUT 512
#define KDIM 4608          // 512*9
#define NANCH 22500
#define NPRE 3000
#define NPOST 300
#define NCHUNK 6
#define CHUNK 4096
#define PADN (NCHUNK*CHUNK)   // 24576

#define OFF_LOCS 0
#define SZ_LOCS (NB*NANCH*4)           // 360000
#define OFF_SCORES (OFF_LOCS+SZ_LOCS)  // 360000
#define SZ_SCORES (NB*NANCH*2)         // 180000
#define OFF_ROIS (OFF_SCORES+SZ_SCORES)// 540000
#define SZ_ROIS (NB*NPOST*4)           // 4800
#define OFF_RIDX (OFF_ROIS+SZ_ROIS)    // 544800
#define SZ_RIDX (NB*NPOST)             // 1200
#define OFF_ANCH (OFF_RIDX+SZ_RIDX)    // 546000

// ---------------- scratch (device globals; no allocation allowed) ----------------
__device__ float g_feat[NB*HW*COUT];                 // NHWC feature map
__device__ float g_boxes[NB*NANCH*4];                // decoded+clipped boxes
__device__ unsigned char g_valid[NB*NANCH];          // min-size validity
__device__ unsigned long long g_keys[NB*PADN];       // sort keys per chunk
__device__ float g_sboxes[NB*NPRE*4];                // top-3000 boxes in exact order
__device__ unsigned char g_svalid[NB*NPRE];          // validity of top-3000

// ---------------- kernel 1: 3x3 conv (implicit-GEMM SGEMM, fp32) ----------------
// M=512 couts, N=2500 px (pad 2560), K=4608. Tile 128x128x8, 256 threads, 8x8 micro.
#define BM 128
#define BN 128
#define KC 8

__global__ __launch_bounds__(256, 2)
void conv3x3_kernel(const float* __restrict__ X, const float* __restrict__ W,
                    const float* __restrict__ bias) {
    __shared__ float As[KC][BM];
    __shared__ float Bs[KC][BN];

    const int pn0 = blockIdx.x * BN;      // pixel tile base
    const int cm0 = blockIdx.y * BM;      // cout tile base
    const int b   = blockIdx.z;
    const int tid = threadIdx.x;
    const int tx  = tid & 15;             // 0..15 -> 8 px each
    const int ty  = tid >> 4;             // 0..15 -> 8 couts each

    const float* Xb = X + b * (CIN * HW);

    // A-load mapping: each thread loads float4 of W
    const int arow = tid >> 1;
    const int acol = (tid & 1) * 4;
    // B-load mapping: each thread loads 4 consecutive pixels of one k row
    const int kl = tid >> 5;              // 0..7
    const int pl = (tid & 31) * 4;        // 0..124

    // precompute pixel coords for the 4 B elements (constant across k-loop)
    int py[4], px[4];
#pragma unroll
    for (int q = 0; q < 4; q++) {
        int p = pn0 + pl + q;
        if (p < HW) { py[q] = p / 50; px[q] = p - py[q] * 50; }
        else        { py[q] = -1000;  px[q] = -1000; }
    }

    float acc[8][8];
#pragma unroll
    for (int i = 0; i < 8; i++)
#pragma unroll
        for (int j = 0; j < 8; j++) acc[i][j] = 0.f;

    for (int k0 = 0; k0 < KDIM; k0 += KC) {
        __syncthreads();
        // load A (weights): As[k][cout]
        float4 av = *(const float4*)(W + (size_t)(cm0 + arow) * KDIM + k0 + acol);
        As[acol + 0][arow] = av.x;
        As[acol + 1][arow] = av.y;
        As[acol + 2][arow] = av.z;
        As[acol + 3][arow] = av.w;
        // load B (im2col input)
        {
            int k = k0 + kl;
            int cin = k / 9, rem = k - cin * 9;
            int ky = rem / 3 - 1, kx = rem - (rem / 3) * 3 - 1;
            const float* Xc = Xb + cin * HW;
#pragma unroll
            for (int q = 0; q < 4; q++) {
                int yy = py[q] + ky, xx = px[q] + kx;
                float v = 0.f;
                if (yy >= 0 && yy < 50 && xx >= 0 && xx < 50) v = Xc[yy * 50 + xx];
                Bs[kl][pl + q] = v;
            }
        }
        __syncthreads();
#pragma unroll
        for (int kk = 0; kk < KC; kk++) {
            float a[8], bb[8];
            float4 a0 = *(float4*)&As[kk][ty * 8];
            float4 a1 = *(float4*)&As[kk][ty * 8 + 4];
            float4 b0 = *(float4*)&Bs[kk][tx * 8];
            float4 b1 = *(float4*)&Bs[kk][tx * 8 + 4];
            a[0]=a0.x; a[1]=a0.y; a[2]=a0.z; a[3]=a0.w;
            a[4]=a1.x; a[5]=a1.y; a[6]=a1.z; a[7]=a1.w;
            bb[0]=b0.x; bb[1]=b0.y; bb[2]=b0.z; bb[3]=b0.w;
            bb[4]=b1.x; bb[5]=b1.y; bb[6]=b1.z; bb[7]=b1.w;
#pragma unroll
            for (int i = 0; i < 8; i++)
#pragma unroll
                for (int j = 0; j < 8; j++)
                    acc[i][j] += a[i] * bb[j];
        }
    }

    // epilogue: bias + relu, store NHWC
    float bz[8];
#pragma unroll
    for (int i = 0; i < 8; i++) bz[i] = bias[cm0 + ty * 8 + i];

#pragma unroll
    for (int j = 0; j < 8; j++) {
        int p = pn0 + tx * 8 + j;
        if (p < HW) {
            float* dst = &g_feat[((size_t)(b * HW + p) << 9) + cm0 + ty * 8];
            float4 v0, v1;
            v0.x = fmaxf(acc[0][j] + bz[0], 0.f);
            v0.y = fmaxf(acc[1][j] + bz[1], 0.f);
            v0.z = fmaxf(acc[2][j] + bz[2], 0.f);
            v0.w = fmaxf(acc[3][j] + bz[3], 0.f);
            v1.x = fmaxf(acc[4][j] + bz[4], 0.f);
            v1.y = fmaxf(acc[5][j] + bz[5], 0.f);
            v1.z = fmaxf(acc[6][j] + bz[6], 0.f);
            v1.w = fmaxf(acc[7][j] + bz[7], 0.f);
            *(float4*)(dst)     = v0;
            *(float4*)(dst + 4) = v1;
        }
    }
}

// ---------------- kernel 2: 1x1 heads (loc 36ch + score 18ch) ----------------
__global__ __launch_bounds__(256)
void heads_kernel(const float* __restrict__ lw, const float* __restrict__ lb,
                  const float* __restrict__ sw, const float* __restrict__ sb,
                  float* __restrict__ out) {
    __shared__ float fs[8 * 512];
    const int b = blockIdx.y;
    const int p0 = blockIdx.x * 8;
    const int tid = threadIdx.x;

    for (int idx = tid * 4; idx < 8 * 512; idx += 256 * 4) {
        int pxi = idx >> 9;
        float4 v = make_float4(0.f, 0.f, 0.f, 0.f);
        if (p0 + pxi < HW)
            v = *(const float4*)&g_feat[((size_t)(b * HW + p0 + pxi) << 9) + (idx & 511)];
        *(float4*)&fs[idx] = v;
    }
    __syncthreads();

    for (int task = tid; task < 8 * 54; task += 256) {
        int pxi = task / 54;
        int o = task - pxi * 54;
        int p = p0 + pxi;
        if (p >= HW) continue;
        const float* wr = (o < 36) ? (lw + (o << 9)) : (sw + ((o - 36) << 9));
        const float* f = &fs[pxi << 9];
        float s = 0.f;
#pragma unroll 8
        for (int c = 0; c < 512; c += 4) {
            float4 wv = *(const float4*)&wr[c];
            float4 fv = *(const float4*)&f[c];
            s += wv.x * fv.x + wv.y * fv.y + wv.z * fv.z + wv.w * fv.w;
        }
        if (o < 36) {
            s += lb[o];
            int a = o >> 2, j = o & 3;
            out[OFF_LOCS + b * (NANCH * 4) + (p * 9 + a) * 4 + j] = s;
        } else {
            int oo = o - 36;
            s += sb[oo];
            int a = oo >> 1, j = oo & 1;
            out[OFF_SCORES + b * (NANCH * 2) + (p * 9 + a) * 2 + j] = s;
        }
    }
}

// ---------------- anchors (match numpy: base in double -> f32, shift add in f32) --
__device__ __forceinline__ void anchor_of(int i, float& ax1, float& ay1, float& ax2, float& ay2) {
    int p = i / 9, a = i - p * 9;
    int y = p / 50, x = p - y * 50;
    int ri = a / 3, si = a - ri * 3;
    const double ratios[3] = {0.5, 1.0, 2.0};
    const double scales[3] = {8.0, 16.0, 32.0};
    double hh = 16.0 * scales[si] * sqrt(ratios[ri]);
    double ww = 16.0 * scales[si] * sqrt(1.0 / ratios[ri]);
    float bx1 = (float)(8.0 - ww / 2.0);
    float by1 = (float)(8.0 - hh / 2.0);
    float bx2 = (float)(8.0 + ww / 2.0);
    float by2 = (float)(8.0 + hh / 2.0);
    float sx = (float)(x * 16);
    float sy = (float)(y * 16);
    ax1 = sx + bx1; ay1 = sy + by1; ax2 = sx + bx2; ay2 = sy + by2;
}

__global__ void anchor_kernel(float* __restrict__ out) {
    int i = blockIdx.x * blockDim.x + threadIdx.x;
    if (i >= NANCH) return;
    float a1, b1, a2, b2;
    anchor_of(i, a1, b1, a2, b2);
    out[OFF_ANCH + i * 4 + 0] = a1;
    out[OFF_ANCH + i * 4 + 1] = b1;
    out[OFF_ANCH + i * 4 + 2] = a2;
    out[OFF_ANCH + i * 4 + 3] = b2;
}

// ---------------- kernel 4: decode + clip + valid + sort keys ----------------
__device__ __forceinline__ float dim_to_float(const int* p) {
    int v = *p;
    if (v > 0 && v < 100000) return (float)v;
    return __int_as_float(v);   // in case the scalar arrived as float bits
}

__global__ void decode_kernel(const float* __restrict__ out,
                              const int* __restrict__ imh, const int* __restrict__ imw) {
    const int b = blockIdx.y;
    const int i = blockIdx.x * blockDim.x + threadIdx.x;
    if (i >= PADN) return;
    unsigned long long key;
    if (i < NANCH) {
        float ax1, ay1, ax2, ay2;
        anchor_of(i, ax1, ay1, ax2, ay2);
        const float* loc = out + OFF_LOCS + b * (NANCH * 4) + i * 4;
        float aw = ax2 - ax1, ah = ay2 - ay1;
        float acx = ax1 + 0.5f * aw, acy = ay1 + 0.5f * ah;
        float cx = loc[0] * aw + acx;
        float cy = loc[1] * ah + acy;
        float ww = expf(loc[2]) * aw;
        float hh = expf(loc[3]) * ah;
        float Wf = dim_to_float(imw), Hf = dim_to_float(imh);
        float x1 = fminf(fmaxf(cx - 0.5f * ww, 0.f), Wf);
        float y1 = fminf(fmaxf(cy - 0.5f * hh, 0.f), Hf);
        float x2 = fminf(fmaxf(cx + 0.5f * ww, 0.f), Wf);
        float y2 = fminf(fmaxf(cy + 0.5f * hh, 0.f), Hf);
        bool valid = (x2 - x1 + 1.f >= 16.f) && (y2 - y1 + 1.f >= 16.f);

        float* bx = &g_boxes[((size_t)b * NANCH + i) * 4];
        bx[0] = x1; bx[1] = y1; bx[2] = x2; bx[3] = y2;
        g_valid[b * NANCH + i] = valid ? 1 : 0;

        const float* sc = out + OFF_SCORES + b * (NANCH * 2) + i * 2;
        float s0 = sc[0], s1 = sc[1];
        float m = fmaxf(s0, s1);
        float e0 = expf(s0 - m), e1 = expf(s1 - m);
        float fg = e1 / (e0 + e1);
        float score = valid ? fg : __int_as_float(0xFF800000);  // -inf
        unsigned u = __float_as_uint(score);
        unsigned s = (u & 0x80000000u) ? ~u : (u | 0x80000000u); // ascending-sortable
        unsigned desc = ~s;                                      // descending score
        key = ((unsigned long long)desc << 32) | (unsigned)i;    // tiebreak: low idx first
    } else {
        key = 0xFFFFFFFFFFFFFFFFull;  // pad: sorts last
    }
    g_keys[(size_t)b * PADN + i] = key;
}

// ---------------- kernel 5: per-chunk bitonic sort (ascending key) ----------------
__global__ __launch_bounds__(512)
void sort_kernel() {
    __shared__ unsigned long long sk[CHUNK];
    const int c = blockIdx.x % NCHUNK;
    const int b = blockIdx.x / NCHUNK;
    unsigned long long* gk = g_keys + (size_t)b * PADN + c * CHUNK;
    for (int i = threadIdx.x; i < CHUNK; i += 512) sk[i] = gk[i];
    __syncthreads();
    for (int k = 2; k <= CHUNK; k <<= 1) {
        for (int j = k >> 1; j > 0; j >>= 1) {
            for (int t = threadIdx.x; t < CHUNK; t += 512) {
                int l = t ^ j;
                if (l > t) {
                    bool up = ((t & k) == 0);
                    unsigned long long a = sk[t], bv = sk[l];
                    if ((a > bv) == up) { sk[t] = bv; sk[l] = a; }
                }
            }
            __syncthreads();
        }
    }
    for (int i = threadIdx.x; i < CHUNK; i += 512) gk[i] = sk[i];
}

// ---------------- kernel 6: co-rank merge -> exact top-3000 in order ----------------
__global__ void merge_kernel() {
    const int b = blockIdx.y;
    const int t = blockIdx.x * blockDim.x + threadIdx.x;
    if (t >= NCHUNK * NPRE) return;
    const int c = t / NPRE;
    const int i = t - c * NPRE;
    const unsigned long long* base = g_keys + (size_t)b * PADN;
    unsigned long long key = base[c * CHUNK + i];
    if ((unsigned)(key >> 32) == 0xFFFFFFFFu) return;  // pad
    int rank = i;
#pragma unroll
    for (int cc = 0; cc < NCHUNK; cc++) {
        if (cc == c) continue;
        const unsigned long long* arr = base + cc * CHUNK;
        int pos = 0;
#pragma unroll
        for (int s = CHUNK / 2; s > 0; s >>= 1)
            if (arr[pos + s - 1] < key) pos += s;
        rank += pos;
    }
    if (rank < NPRE) {
        int idx = (int)(key & 0xFFFFFFFFull);
        int o = b * NPRE + rank;
        const float* src = &g_boxes[((size_t)b * NANCH + idx) * 4];
        float4 v = *(const float4*)src;
        ((float4*)g_sboxes)[o] = v;
        g_svalid[o] = g_valid[b * NANCH + idx];
    }
}

// ---------------- kernel 7: greedy NMS + output assembly ----------------
__global__ __launch_bounds__(1024)
void nms_kernel(float* __restrict__ out) {
    const int b = blockIdx.x;
    const int tid = threadIdx.x;
    __shared__ float4 box[NPRE];          // 48000 B
    __shared__ unsigned mk[(NPRE + 31) / 32]; // 94 words

    for (int i = tid; i < NPRE; i += 1024)
        box[i] = ((const float4*)g_sboxes)[b * NPRE + i];
    for (int w = tid; w < (NPRE + 31) / 32; w += 1024) {
        unsigned m = 0;
        for (int q = 0; q < 32; q++) {
            int j = w * 32 + q;
            if (j < NPRE && g_svalid[b * NPRE + j]) m |= (1u << q);
        }
        mk[w] = m;
    }
    __syncthreads();

    for (int i = 0; i < NPRE - 1; i++) {
        bool keep = (mk[i >> 5] >> (i & 31)) & 1;
        if (keep) {
            float4 bi = box[i];
            float ai = (bi.z - bi.x) * (bi.w - bi.y);
            for (int j = i + 1 + tid; j < NPRE; j += 1024) {
                float4 bj = box[j];
                float iw = fminf(bi.z, bj.z) - fmaxf(bi.x, bj.x);
                float ih = fminf(bi.w, bj.w) - fmaxf(bi.y, bj.y);
                iw = fmaxf(iw, 0.f); ih = fmaxf(ih, 0.f);
                float inter = iw * ih;
                float aj = (bj.z - bj.x) * (bj.w - bj.y);
                float iou = inter / (ai + aj - inter + 1e-9f);
                if (iou > 0.7f) atomicAnd(&mk[j >> 5], ~(1u << (j & 31)));
            }
        }
        __syncthreads();
    }

    // zero rois region, write roi_indices
    for (int q = tid; q < NPOST * 4; q += 1024) out[OFF_ROIS + b * (NPOST * 4) + q] = 0.f;
    for (int q = tid; q < NPOST; q += 1024) out[OFF_RIDX + b * NPOST + q] = (float)b;
    __syncthreads();

    // ordered compaction by warp 0 (stable argsort: kept boxes in rank order)
    if (tid < 32) {
        int cnt = 0;
        for (int w0 = 0; w0 < (NPRE + 31) / 32; w0++) {
            unsigned flags = mk[w0];
            int j = w0 * 32 + tid;
            bool f = (flags >> tid) & 1;
            int pos = cnt + __popc(flags & ((1u << tid) - 1u));
            if (f && pos < NPOST) {
                float4 bb = box[j];
                float* o = out + OFF_ROIS + b * (NPOST * 4) + pos * 4;
                o[0] = bb.x; o[1] = bb.y; o[2] = bb.z; o[3] = bb.w;
            }
            cnt += __popc(flags);
            if (cnt >= NPOST) break;
        }
    }
}

// ---------------- launcher ----------------
extern "C" void kernel_launch(void* const* d_in, const int* in_sizes, int n_in,
                              void* d_out, int out_size) {
    const float* x  = (const float*)d_in[0];
    const float* w1 = (const float*)d_in[1];
    const float* b1 = (const float*)d_in[2];
    const float* lw = (const float*)d_in[3];
    const float* lb = (const float*)d_in[4];
    const float* sw = (const float*)d_in[5];
    const float* sb = (const float*)d_in[6];
    const int* ih   = (const int*)d_in[7];
    const int* iw   = (const int*)d_in[8];
    float* out = (float*)d_out;

    conv3x3_kernel<<<dim3((HW + BN - 1) / BN, COUT / BM, NB), 256>>>(x, w1, b1);
    heads_kernel<<<dim3((HW + 7) / 8, NB), 256>>>(lw, lb, sw, sb, out);
    anchor_kernel<<<(NANCH + 255) / 256, 256>>>(out);
    decode_kernel<<<dim3((PADN + 255) / 256, NB), 256>>>(out, ih, iw);
    sort_kernel<<<NB * NCHUNK, 512>>>();
    merge_kernel<<<dim3((NCHUNK * NPRE + 255) / 256, NB), 256>>>();
    nms_kernel<<<NB, 1024>>>(out);
}

// round 6
// speedup vs baseline: 2.7283x; 2.7253x over previous
#include <cuda_runtime.h>
#include <cuda_fp16.h>
#include <math.h>
#include <stdint.h>

#define NB 4
#define HW 2500
#define CIN 512
#define COUT 512
#define KDIM 4608
#define NANCH 22500
#define NPRE 3000
#define NPOST 300
#define NCHUNK 6
#define CHUNK 4096
#define PADN (NCHUNK*CHUNK)

#define OFF_LOCS 0
#define OFF_SCORES (NB*NANCH*4)
#define OFF_ROIS (OFF_SCORES+NB*NANCH*2)
#define OFF_RIDX (OFF_ROIS+NB*NPOST*4)
#define OFF_ANCH (OFF_RIDX+NB*NPOST)

#define WPAD 56
#define PLANE 3072
#define KC 64
#define NKC 72
#define NTILES_N 22
#define BUFB 98304u
#define CONV_SMEM (2*98304)
#define XSCALE 256.0f
#define WSCALE 64.0f
#define UNSCALE (1.0f/16384.0f)

// ---------------- scratch ----------------
__device__ __align__(16) __half g_xh[3][3][(size_t)NB*CIN*PLANE];
__device__ __align__(16) __half g_wh[3][(size_t)COUT*KDIM];
__device__ float g_feat[(size_t)NB*HW*COUT];
__device__ float g_boxes[NB*NANCH*4];
__device__ unsigned char g_valid[NB*NANCH];
__device__ unsigned long long g_keys[NB*PADN];
__device__ float g_sboxes[NB*NPRE*4];
__device__ unsigned char g_svalid[NB*NPRE];
__device__ unsigned g_sup[NB][3008][96];

// ---------------- PTX helpers ----------------
__device__ __forceinline__ uint32_t smem_u32(const void* p) {
    uint32_t a;
    asm("{ .reg .u64 t; cvta.to.shared.u64 t, %1; cvt.u32.u64 %0, t; }" : "=r"(a) : "l"(p));
    return a;
}
__device__ __forceinline__ void cp16(uint32_t dst, const void* src) {
    asm volatile("cp.async.cg.shared.global [%0], [%1], 16;" :: "r"(dst), "l"(src) : "memory");
}
#define CP_COMMIT() asm volatile("cp.async.commit_group;" ::: "memory")
#define CP_WAIT(n)  asm volatile("cp.async.wait_group %0;" :: "n"(n) : "memory")

__device__ __forceinline__ void ldsm4(uint32_t* r, uint32_t a) {
    asm volatile("ldmatrix.sync.aligned.m8n8.x4.shared.b16 {%0,%1,%2,%3}, [%4];"
        : "=r"(r[0]), "=r"(r[1]), "=r"(r[2]), "=r"(r[3]) : "r"(a));
}
__device__ __forceinline__ void ldsm4t(uint32_t* r, uint32_t a) {
    asm volatile("ldmatrix.sync.aligned.m8n8.x4.trans.shared.b16 {%0,%1,%2,%3}, [%4];"
        : "=r"(r[0]), "=r"(r[1]), "=r"(r[2]), "=r"(r[3]) : "r"(a));
}
__device__ __forceinline__ void mma16816(float* c, const uint32_t* a, const uint32_t* b) {
    asm volatile("mma.sync.aligned.m16n8k16.row.col.f32.f16.f16.f32 "
        "{%0,%1,%2,%3}, {%4,%5,%6,%7}, {%8,%9}, {%0,%1,%2,%3};"
        : "+f"(c[0]), "+f"(c[1]), "+f"(c[2]), "+f"(c[3])
        : "r"(a[0]), "r"(a[1]), "r"(a[2]), "r"(a[3]), "r"(b[0]), "r"(b[1]));
}

// ---------------- splits (scaled 3-term fp16) ----------------
__global__ void split_x_kernel(const float* __restrict__ X) {
    const int bc = blockIdx.x;
    const float* src = X + (size_t)bc * HW;
    for (int idx = threadIdx.x; idx < PLANE; idx += 256) {
        int yy = idx / WPAD, xx = idx - yy * WPAD;
        int iy = yy - 1;
#pragma unroll
        for (int kx = 0; kx < 3; kx++) {
            int ix = xx + kx - 1;
            float v = 0.f;
            if (iy >= 0 && iy < 50 && ix >= 0 && ix < 50) v = src[iy * 50 + ix];
            v *= XSCALE;
            __half h0 = __float2half(v);
            float r1 = v - __half2float(h0);
            __half h1 = __float2half(r1);
            __half h2 = __float2half(r1 - __half2float(h1));
            size_t o = (size_t)bc * PLANE + idx;
            g_xh[0][kx][o] = h0; g_xh[1][kx][o] = h1; g_xh[2][kx][o] = h2;
        }
    }
}
__global__ void split_w_kernel(const float* __restrict__ W) {
    int i = blockIdx.x * 256 + threadIdx.x;
    if (i >= COUT * KDIM) return;
    float v = W[i] * WSCALE;
    __half h0 = __float2half(v);
    float r1 = v - __half2float(h0);
    __half h1 = __float2half(r1);
    g_wh[0][i] = h0; g_wh[1][i] = h1;
    g_wh[2][i] = __float2half(r1 - __half2float(h1));
}

// ---------------- conv 3x3 via mma.sync: 3-term split, 6 products, per-chunk flush ----
__global__ __launch_bounds__(256, 1)
void conv_mma_kernel(const float* __restrict__ bias) {
    extern __shared__ char dsm[];
    const uint32_t sbase = smem_u32(dsm);
    const int tid = threadIdx.x;
    const int lane = tid & 31, warp = tid >> 5;
    const int p0 = blockIdx.x * 128;
    const int m0 = blockIdx.y * 128;
    const int b  = blockIdx.z;
    const int warp_m = (warp >> 2) * 64;
    const int warp_n = (warp & 3) * 32;

    float C[4][4][4];   // per-chunk MMA accumulators (flushed)
    float S[4][4][4];   // long-run fp32 sums (RN adds)
#pragma unroll
    for (int i = 0; i < 4; i++)
#pragma unroll
        for (int j = 0; j < 4; j++)
#pragma unroll
            for (int r = 0; r < 4; r++) { C[i][j][r] = 0.f; S[i][j][r] = 0.f; }

    const int m_lane = lane & 15, hi = lane >> 4;
    const int nb = warp_n >> 3;

    auto load_stage = [&](int kc, uint32_t base) {
        const int k0 = kc * KC;
#pragma unroll
        for (int s = 0; s < 3; s++) {
            const __half* wsrc = g_wh[s];
#pragma unroll
            for (int it = 0; it < 4; it++) {
                int idx = tid + it * 256;
                int m = idx >> 3, c = idx & 7;
                cp16(base + (uint32_t)s * 16384u + (uint32_t)m * 128u + (uint32_t)((c ^ (m & 7)) << 4),
                     wsrc + (size_t)(m0 + m) * KDIM + k0 + c * 8);
            }
#pragma unroll
            for (int it = 0; it < 4; it++) {
                int idx = tid + it * 256;
                int k = idx >> 4, c = idx & 15;
                int kk = k0 + k;
                int cin = kk / 9, rem = kk - cin * 9;
                int ky = rem / 3, kx = rem - ky * 3;
                const __half* src = &g_xh[s][kx][(size_t)(b * CIN + cin) * PLANE + ky * WPAD + p0 + c * 8];
                cp16(base + 49152u + (uint32_t)s * 16384u + (uint32_t)k * 256u + (uint32_t)((c ^ (k & 7)) << 4), src);
            }
        }
        CP_COMMIT();
    };

    load_stage(0, sbase);

    for (int kc = 0; kc < NKC; kc++) {
        const uint32_t cur = sbase + (uint32_t)(kc & 1) * BUFB;
        if (kc + 1 < NKC) {
            load_stage(kc + 1, sbase + (uint32_t)((kc + 1) & 1) * BUFB);
            CP_WAIT(1);
        } else {
            CP_WAIT(0);
        }
        __syncthreads();

        const uint32_t sA0 = cur, sA1 = cur + 16384u, sA2 = cur + 32768u;
        const uint32_t sB0 = cur + 49152u, sB1 = cur + 65536u, sB2 = cur + 81920u;
#pragma unroll
        for (int ks = 0; ks < 4; ks++) {
            uint32_t a0f[4][4], a1f[4][4], a2f[4][4], b0f[2][4], b1f[2][4], b2f[2][4];
#pragma unroll
            for (int mi = 0; mi < 4; mi++) {
                int m = warp_m + mi * 16 + m_lane;
                uint32_t off = (uint32_t)m * 128u + (uint32_t)(((ks * 2 + hi) ^ (m_lane & 7)) << 4);
                ldsm4(a0f[mi], sA0 + off);
                ldsm4(a1f[mi], sA1 + off);
                ldsm4(a2f[mi], sA2 + off);
            }
#pragma unroll
            for (int ni = 0; ni < 2; ni++) {
                int k = ks * 16 + m_lane;
                uint32_t off = (uint32_t)k * 256u + (uint32_t)(((nb + ni * 2 + hi) ^ (m_lane & 7)) << 4);
                ldsm4t(b0f[ni], sB0 + off);
                ldsm4t(b1f[ni], sB1 + off);
                ldsm4t(b2f[ni], sB2 + off);
            }
#pragma unroll
            for (int mi = 0; mi < 4; mi++)
#pragma unroll
                for (int g = 0; g < 4; g++) {
                    float* cc = C[mi][g];
                    const uint32_t* pb0 = &b0f[g >> 1][(g & 1) * 2];
                    const uint32_t* pb1 = &b1f[g >> 1][(g & 1) * 2];
                    const uint32_t* pb2 = &b2f[g >> 1][(g & 1) * 2];
                    mma16816(cc, a0f[mi], pb0);
                    mma16816(cc, a0f[mi], pb1);
                    mma16816(cc, a1f[mi], pb0);
                    mma16816(cc, a1f[mi], pb1);
                    mma16816(cc, a2f[mi], pb0);
                    mma16816(cc, a0f[mi], pb2);
                }
        }
        // flush: fold chunk partials into S with RN adds, reset C
#pragma unroll
        for (int mi = 0; mi < 4; mi++)
#pragma unroll
            for (int g = 0; g < 4; g++)
#pragma unroll
                for (int r = 0; r < 4; r++) {
                    S[mi][g][r] += C[mi][g][r];
                    C[mi][g][r] = 0.f;
                }
        __syncthreads();
    }

    float bz[4][2];
#pragma unroll
    for (int mi = 0; mi < 4; mi++)
#pragma unroll
        for (int h = 0; h < 2; h++)
            bz[mi][h] = bias[m0 + warp_m + mi * 16 + (lane >> 2) + 8 * h];

#pragma unroll
    for (int mi = 0; mi < 4; mi++)
#pragma unroll
        for (int g = 0; g < 4; g++)
#pragma unroll
            for (int r = 0; r < 4; r++) {
                int pp = p0 + warp_n + g * 8 + (lane & 3) * 2 + (r & 1);
                int y = pp / WPAD, x = pp - y * WPAD;
                if (x < 50 && y < 50) {
                    int m = m0 + warp_m + mi * 16 + (lane >> 2) + 8 * (r >> 1);
                    g_feat[((size_t)(b * HW + y * 50 + x) << 9) + m] =
                        fmaxf(S[mi][g][r] * UNSCALE + bz[mi][r >> 1], 0.f);
                }
            }
}

// ---------------- 1x1 heads ----------------
__global__ __launch_bounds__(256)
void heads_kernel(const float* __restrict__ lw, const float* __restrict__ lb,
                  const float* __restrict__ sw, const float* __restrict__ sb,
                  float* __restrict__ out) {
    __shared__ float fs[8 * 512];
    const int b = blockIdx.y, p0 = blockIdx.x * 8, tid = threadIdx.x;
    for (int idx = tid * 4; idx < 8 * 512; idx += 1024) {
        int pxi = idx >> 9;
        float4 v = make_float4(0.f, 0.f, 0.f, 0.f);
        if (p0 + pxi < HW) v = *(const float4*)&g_feat[((size_t)(b * HW + p0 + pxi) << 9) + (idx & 511)];
        *(float4*)&fs[idx] = v;
    }
    __syncthreads();
    for (int task = tid; task < 8 * 54; task += 256) {
        int pxi = task / 54, o = task - pxi * 54, p = p0 + pxi;
        if (p >= HW) continue;
        const float* wr = (o < 36) ? (lw + (o << 9)) : (sw + ((o - 36) << 9));
        const float* f = &fs[pxi << 9];
        float s = 0.f;
#pragma unroll 8
        for (int c = 0; c < 512; c += 4) {
            float4 wv = *(const float4*)&wr[c];
            float4 fv = *(const float4*)&f[c];
            s += wv.x * fv.x + wv.y * fv.y + wv.z * fv.z + wv.w * fv.w;
        }
        if (o < 36) {
            int a = o >> 2, j = o & 3;
            out[OFF_LOCS + b * (NANCH * 4) + (p * 9 + a) * 4 + j] = s + lb[o];
        } else {
            int oo = o - 36, a = oo >> 1, j = oo & 1;
            out[OFF_SCORES + b * (NANCH * 2) + (p * 9 + a) * 2 + j] = s + sb[oo];
        }
    }
}

// ---------------- anchors ----------------
__device__ __forceinline__ void anchor_of(int i, float& ax1, float& ay1, float& ax2, float& ay2) {
    int p = i / 9, a = i - p * 9;
    int y = p / 50, x = p - y * 50;
    int ri = a / 3, si = a - ri * 3;
    const double ratios[3] = {0.5, 1.0, 2.0};
    const double scales[3] = {8.0, 16.0, 32.0};
    double hh = 16.0 * scales[si] * sqrt(ratios[ri]);
    double ww = 16.0 * scales[si] * sqrt(1.0 / ratios[ri]);
    float sx = (float)(x * 16), sy = (float)(y * 16);
    ax1 = sx + (float)(8.0 - ww / 2.0); ay1 = sy + (float)(8.0 - hh / 2.0);
    ax2 = sx + (float)(8.0 + ww / 2.0); ay2 = sy + (float)(8.0 + hh / 2.0);
}
__global__ void anchor_kernel(float* __restrict__ out) {
    int i = blockIdx.x * blockDim.x + threadIdx.x;
    if (i >= NANCH) return;
    float a1, b1, a2, b2;
    anchor_of(i, a1, b1, a2, b2);
    out[OFF_ANCH + i * 4 + 0] = a1; out[OFF_ANCH + i * 4 + 1] = b1;
    out[OFF_ANCH + i * 4 + 2] = a2; out[OFF_ANCH + i * 4 + 3] = b2;
}

// ---------------- decode + keys ----------------
__device__ __forceinline__ float dim_to_float(const int* p) {
    int v = *p;
    if (v > 0 && v < 100000) return (float)v;
    return __int_as_float(v);
}
__global__ void decode_kernel(const float* __restrict__ out,
                              const int* __restrict__ imh, const int* __restrict__ imw) {
    const int b = blockIdx.y;
    const int i = blockIdx.x * blockDim.x + threadIdx.x;
    if (i >= PADN) return;
    unsigned long long key;
    if (i < NANCH) {
        float ax1, ay1, ax2, ay2;
        anchor_of(i, ax1, ay1, ax2, ay2);
        const float* loc = out + OFF_LOCS + b * (NANCH * 4) + i * 4;
        float aw = ax2 - ax1, ah = ay2 - ay1;
        float cx = loc[0] * aw + ax1 + 0.5f * aw;
        float cy = loc[1] * ah + ay1 + 0.5f * ah;
        float ww = expf(loc[2]) * aw, hh = expf(loc[3]) * ah;
        float Wf = dim_to_float(imw), Hf = dim_to_float(imh);
        float x1 = fminf(fmaxf(cx - 0.5f * ww, 0.f), Wf);
        float y1 = fminf(fmaxf(cy - 0.5f * hh, 0.f), Hf);
        float x2 = fminf(fmaxf(cx + 0.5f * ww, 0.f), Wf);
        float y2 = fminf(fmaxf(cy + 0.5f * hh, 0.f), Hf);
        bool valid = (x2 - x1 + 1.f >= 16.f) && (y2 - y1 + 1.f >= 16.f);
        float* bx = &g_boxes[((size_t)b * NANCH + i) * 4];
        bx[0] = x1; bx[1] = y1; bx[2] = x2; bx[3] = y2;
        g_valid[b * NANCH + i] = valid ? 1 : 0;
        const float* sc = out + OFF_SCORES + b * (NANCH * 2) + i * 2;
        float s0 = sc[0], s1 = sc[1];
        float m = fmaxf(s0, s1);
        float e0 = expf(s0 - m), e1 = expf(s1 - m);
        float fg = e1 / (e0 + e1);
        float score = valid ? fg : __int_as_float(0xFF800000);
        unsigned u = __float_as_uint(score);
        unsigned s = (u & 0x80000000u) ? ~u : (u | 0x80000000u);
        key = ((unsigned long long)(~s) << 32) | (unsigned)i;
    } else key = 0xFFFFFFFFFFFFFFFFull;
    g_keys[(size_t)b * PADN + i] = key;
}

// ---------------- per-chunk bitonic sort ----------------
__global__ __launch_bounds__(512)
void sort_kernel() {
    __shared__ unsigned long long sk[CHUNK];
    const int c = blockIdx.x % NCHUNK, b = blockIdx.x / NCHUNK;
    unsigned long long* gk = g_keys + (size_t)b * PADN + c * CHUNK;
    for (int i = threadIdx.x; i < CHUNK; i += 512) sk[i] = gk[i];
    __syncthreads();
    for (int k = 2; k <= CHUNK; k <<= 1)
        for (int j = k >> 1; j > 0; j >>= 1) {
            for (int t = threadIdx.x; t < CHUNK; t += 512) {
                int l = t ^ j;
                if (l > t) {
                    bool up = ((t & k) == 0);
                    unsigned long long a = sk[t], bv = sk[l];
                    if ((a > bv) == up) { sk[t] = bv; sk[l] = a; }
                }
            }
            __syncthreads();
        }
    for (int i = threadIdx.x; i < CHUNK; i += 512) gk[i] = sk[i];
}

// ---------------- co-rank merge -> exact top-3000 ----------------
__global__ void merge_kernel() {
    const int b = blockIdx.y;
    const int t = blockIdx.x * blockDim.x + threadIdx.x;
    if (t >= NCHUNK * NPRE) return;
    const int c = t / NPRE, i = t - c * NPRE;
    const unsigned long long* base = g_keys + (size_t)b * PADN;
    unsigned long long key = base[c * CHUNK + i];
    if ((unsigned)(key >> 32) == 0xFFFFFFFFu) return;
    int rank = i;
#pragma unroll
    for (int cc = 0; cc < NCHUNK; cc++) {
        if (cc == c) continue;
        const unsigned long long* arr = base + cc * CHUNK;
        int pos = 0;
#pragma unroll
        for (int s = CHUNK / 2; s > 0; s >>= 1)
            if (arr[pos + s - 1] < key) pos += s;
        rank += pos;
    }
    if (rank < NPRE) {
        int idx = (int)(key & 0xFFFFFFFFull);
        int o = b * NPRE + rank;
        ((float4*)g_sboxes)[o] = *(const float4*)&g_boxes[((size_t)b * NANCH + idx) * 4];
        g_svalid[o] = g_valid[b * NANCH + idx];
    }
}

// ---------------- NMS: suppression bitmatrix ----------------
__global__ __launch_bounds__(1024)
void nms_build_kernel() {
    __shared__ float4 bx[NPRE];
    const int b = blockIdx.y, tid = threadIdx.x;
    const int lane = tid & 31, warp = tid >> 5;
    for (int idx = tid; idx < NPRE; idx += 1024)
        bx[idx] = ((const float4*)g_sboxes)[b * NPRE + idx];
    __syncthreads();
    int i = blockIdx.x * 32 + warp;
    if (i >= NPRE) return;
    float4 bi = bx[i];
    float ai = (bi.z - bi.x) * (bi.w - bi.y);
    for (int jw = 0; jw < 94; jw++) {
        int j = jw * 32 + lane;
        bool sup = false;
        if (j < NPRE && j > i) {
            float4 bj = bx[j];
            float iw = fmaxf(fminf(bi.z, bj.z) - fmaxf(bi.x, bj.x), 0.f);
            float ih = fmaxf(fminf(bi.w, bj.w) - fmaxf(bi.y, bj.y), 0.f);
            float inter = iw * ih;
            float aj = (bj.z - bj.x) * (bj.w - bj.y);
            sup = inter / (ai + aj - inter + 1e-9f) > 0.7f;
        }
        unsigned word = __ballot_sync(0xFFFFFFFFu, sup);
        if (lane == 0) g_sup[b][i][jw] = word;
    }
    if (lane < 2) g_sup[b][i][94 + lane] = 0;
}

// ---------------- NMS: single-warp greedy scan + output ----------------
#define STILE 64
__global__ __launch_bounds__(256)
void nms_scan_kernel(float* __restrict__ out) {
    extern __shared__ unsigned srows[];
    __shared__ unsigned keepw[96];
    const int b = blockIdx.x, tid = threadIdx.x;
    const int lane = tid & 31, warp = tid >> 5;

    for (int w = tid; w < 96; w += 256) {
        unsigned word = 0;
        for (int q = 0; q < 32; q++) {
            int idx = w * 32 + q;
            if (idx < NPRE && g_svalid[b * NPRE + idx]) word |= (1u << q);
        }
        keepw[w] = word;
    }
    for (int idx = tid; idx < STILE * 24; idx += 256) {
        int i = idx / 24, w4 = idx % 24;
        uint4 v = make_uint4(0, 0, 0, 0);
        if (i < NPRE) v = ((const uint4*)g_sup[b][i])[w4];
        ((uint4*)srows)[idx] = v;
    }
    __syncthreads();

    const int ntiles = (NPRE + STILE - 1) / STILE;
    for (int t = 0; t < ntiles; t++) {
        if (warp > 0 && t + 1 < ntiles) {
            unsigned* buf = srows + ((t + 1) & 1) * STILE * 96;
            for (int idx = tid - 32; idx < STILE * 24; idx += 224) {
                int i = (t + 1) * STILE + idx / 24, w4 = idx % 24;
                uint4 v = make_uint4(0, 0, 0, 0);
                if (i < NPRE) v = ((const uint4*)g_sup[b][i])[w4];
                ((uint4*)buf)[idx] = v;
            }
        }
        if (warp == 0) {
            const unsigned* buf = srows + (t & 1) * STILE * 96;
            unsigned wcur = 0;
            for (int ii = 0; ii < STILE; ii++) {
                int i = t * STILE + ii;
                if (i >= NPRE) break;
                int cw = i >> 5, bit = i & 31;
                if (bit == 0) { __syncwarp(); wcur = keepw[cw]; }
                if ((wcur >> bit) & 1) {
                    const unsigned* row = buf + ii * 96;
                    wcur &= ~row[cw];
                    keepw[lane]      &= ~row[lane];
                    keepw[lane + 32] &= ~row[lane + 32];
                    keepw[lane + 64] &= ~row[lane + 64];
                }
            }
        }
        __syncthreads();
    }

    for (int q = tid; q < NPOST * 4; q += 256) out[OFF_ROIS + b * (NPOST * 4) + q] = 0.f;
    for (int q = tid; q < NPOST; q += 256) out[OFF_RIDX + b * NPOST + q] = (float)b;
    __syncthreads();

    if (warp == 0) {
        int cnt = 0;
        for (int w0 = 0; w0 < 94; w0++) {
            unsigned flags = keepw[w0];
            int j = w0 * 32 + lane;
            bool f = (flags >> lane) & 1;
            int pos = cnt + __popc(flags & ((1u << lane) - 1u));
            if (f && pos < NPOST && j < NPRE) {
                float4 bb = ((const float4*)g_sboxes)[b * NPRE + j];
                float* o = out + OFF_ROIS + b * (NPOST * 4) + pos * 4;
                o[0] = bb.x; o[1] = bb.y; o[2] = bb.z; o[3] = bb.w;
            }
            cnt += __popc(flags);
            if (cnt >= NPOST) break;
        }
    }
}

// ---------------- launcher ----------------
extern "C" void kernel_launch(void* const* d_in, const int* in_sizes, int n_in,
                              void* d_out, int out_size) {
    const float* x  = (const float*)d_in[0];
    const float* w1 = (const float*)d_in[1];
    const float* b1 = (const float*)d_in[2];
    const float* lw = (const float*)d_in[3];
    const float* lb = (const float*)d_in[4];
    const float* sw = (const float*)d_in[5];
    const float* sb = (const float*)d_in[6];
    const int* ih   = (const int*)d_in[7];
    const int* iw   = (const int*)d_in[8];
    float* out = (float*)d_out;

    cudaFuncSetAttribute(conv_mma_kernel, cudaFuncAttributeMaxDynamicSharedMemorySize, CONV_SMEM);
    cudaFuncSetAttribute(nms_scan_kernel, cudaFuncAttributeMaxDynamicSharedMemorySize, 2 * STILE * 96 * 4);

    split_x_kernel<<<NB * CIN, 256>>>(x);
    split_w_kernel<<<(COUT * KDIM + 255) / 256, 256>>>(w1);
    conv_mma_kernel<<<dim3(NTILES_N, 4, NB), 256, CONV_SMEM>>>(b1);
    heads_kernel<<<dim3((HW + 7) / 8, NB), 256>>>(lw, lb, sw, sb, out);
    anchor_kernel<<<(NANCH + 255) / 256, 256>>>(out);
    decode_kernel<<<dim3((PADN + 255) / 256, NB), 256>>>(out, ih, iw);
    sort_kernel<<<NB * NCHUNK, 512>>>();
    merge_kernel<<<dim3((NCHUNK * NPRE + 255) / 256, NB), 256>>>();
    nms_build_kernel<<<dim3((NPRE + 31) / 32, NB), 1024>>>();
    nms_scan_kernel<<<NB, 256, 2 * STILE * 96 * 4>>>(out);
}

// round 7
// speedup vs baseline: 3.1806x; 1.1658x over previous
#include <cuda_runtime.h>
#include <cuda_fp16.h>
#include <math.h>
#include <stdint.h>

#define NB 4
#define HW 2500
#define CIN 512
#define COUT 512
#define KDIM 4608
#define NANCH 22500
#define NPRE 3000
#define NPOST 300
#define NCHUNK 6
#define CHUNK 4096
#define PADN (NCHUNK*CHUNK)

#define OFF_LOCS 0
#define OFF_SCORES (NB*NANCH*4)
#define OFF_ROIS (OFF_SCORES+NB*NANCH*2)
#define OFF_RIDX (OFF_ROIS+NB*NPOST*4)
#define OFF_ANCH (OFF_RIDX+NB*NPOST)

#define WPAD 56
#define PLANE 3072
#define KC 64
#define NKC 72
#define NTILES_N 22
#define BUFB 98304u
#define CONV_SMEM (2*98304)
#define XSCALE 256.0f
#define WSCALE 64.0f
#define UNSCALE (1.0f/16384.0f)
#define HEADS_SMEM (128*33*16)

// ---------------- scratch ----------------
__device__ __align__(16) __half g_xh[3][3][(size_t)NB*CIN*PLANE];
__device__ __align__(16) __half g_wh[3][(size_t)COUT*KDIM];
__device__ float g_feat[(size_t)NB*HW*COUT];
__device__ float g_boxes[NB*NANCH*4];
__device__ unsigned char g_valid[NB*NANCH];
__device__ unsigned long long g_keys[NB*PADN];
__device__ float g_sboxes[NB*NPRE*4];
__device__ unsigned char g_svalid[NB*NPRE];
__device__ unsigned g_sup[NB][3008][96];

// ---------------- PTX helpers ----------------
__device__ __forceinline__ uint32_t smem_u32(const void* p) {
    uint32_t a;
    asm("{ .reg .u64 t; cvta.to.shared.u64 t, %1; cvt.u32.u64 %0, t; }" : "=r"(a) : "l"(p));
    return a;
}
__device__ __forceinline__ void cp16(uint32_t dst, const void* src) {
    asm volatile("cp.async.cg.shared.global [%0], [%1], 16;" :: "r"(dst), "l"(src) : "memory");
}
#define CP_COMMIT() asm volatile("cp.async.commit_group;" ::: "memory")
#define CP_WAIT(n)  asm volatile("cp.async.wait_group %0;" :: "n"(n) : "memory")

__device__ __forceinline__ void ldsm4(uint32_t* r, uint32_t a) {
    asm volatile("ldmatrix.sync.aligned.m8n8.x4.shared.b16 {%0,%1,%2,%3}, [%4];"
        : "=r"(r[0]), "=r"(r[1]), "=r"(r[2]), "=r"(r[3]) : "r"(a));
}
__device__ __forceinline__ void ldsm4t(uint32_t* r, uint32_t a) {
    asm volatile("ldmatrix.sync.aligned.m8n8.x4.trans.shared.b16 {%0,%1,%2,%3}, [%4];"
        : "=r"(r[0]), "=r"(r[1]), "=r"(r[2]), "=r"(r[3]) : "r"(a));
}
__device__ __forceinline__ void mma16816(float* c, const uint32_t* a, const uint32_t* b) {
    asm volatile("mma.sync.aligned.m16n8k16.row.col.f32.f16.f16.f32 "
        "{%0,%1,%2,%3}, {%4,%5,%6,%7}, {%8,%9}, {%0,%1,%2,%3};"
        : "+f"(c[0]), "+f"(c[1]), "+f"(c[2]), "+f"(c[3])
        : "r"(a[0]), "r"(a[1]), "r"(a[2]), "r"(a[3]), "r"(b[0]), "r"(b[1]));
}

// ---------------- splits (scaled 3-term fp16) ----------------
__global__ void split_x_kernel(const float* __restrict__ X) {
    const int bc = blockIdx.x;
    const float* src = X + (size_t)bc * HW;
    for (int idx = threadIdx.x; idx < PLANE; idx += 256) {
        int yy = idx / WPAD, xx = idx - yy * WPAD;
        int iy = yy - 1;
#pragma unroll
        for (int kx = 0; kx < 3; kx++) {
            int ix = xx + kx - 1;
            float v = 0.f;
            if (iy >= 0 && iy < 50 && ix >= 0 && ix < 50) v = src[iy * 50 + ix];
            v *= XSCALE;
            __half h0 = __float2half(v);
            float r1 = v - __half2float(h0);
            __half h1 = __float2half(r1);
            __half h2 = __float2half(r1 - __half2float(h1));
            size_t o = (size_t)bc * PLANE + idx;
            g_xh[0][kx][o] = h0; g_xh[1][kx][o] = h1; g_xh[2][kx][o] = h2;
        }
    }
}
__global__ void split_w_kernel(const float* __restrict__ W) {
    int i = blockIdx.x * 256 + threadIdx.x;
    if (i >= COUT * KDIM) return;
    float v = W[i] * WSCALE;
    __half h0 = __float2half(v);
    float r1 = v - __half2float(h0);
    __half h1 = __float2half(r1);
    g_wh[0][i] = h0; g_wh[1][i] = h1;
    g_wh[2][i] = __float2half(r1 - __half2float(h1));
}

// ---------------- conv 3x3 via mma.sync: 3-term split, 6 products, per-chunk flush ----
__global__ __launch_bounds__(256, 1)
void conv_mma_kernel(const float* __restrict__ bias) {
    extern __shared__ char dsm[];
    const uint32_t sbase = smem_u32(dsm);
    const int tid = threadIdx.x;
    const int lane = tid & 31, warp = tid >> 5;
    const int p0 = blockIdx.x * 128;
    const int m0 = blockIdx.y * 128;
    const int b  = blockIdx.z;
    const int warp_m = (warp >> 2) * 64;
    const int warp_n = (warp & 3) * 32;

    float C[4][4][4];
    float S[4][4][4];
#pragma unroll
    for (int i = 0; i < 4; i++)
#pragma unroll
        for (int j = 0; j < 4; j++)
#pragma unroll
            for (int r = 0; r < 4; r++) { C[i][j][r] = 0.f; S[i][j][r] = 0.f; }

    const int m_lane = lane & 15, hi = lane >> 4;
    const int nb = warp_n >> 3;

    auto load_stage = [&](int kc, uint32_t base) {
        const int k0 = kc * KC;
#pragma unroll
        for (int s = 0; s < 3; s++) {
            const __half* wsrc = g_wh[s];
#pragma unroll
            for (int it = 0; it < 4; it++) {
                int idx = tid + it * 256;
                int m = idx >> 3, c = idx & 7;
                cp16(base + (uint32_t)s * 16384u + (uint32_t)m * 128u + (uint32_t)((c ^ (m & 7)) << 4),
                     wsrc + (size_t)(m0 + m) * KDIM + k0 + c * 8);
            }
#pragma unroll
            for (int it = 0; it < 4; it++) {
                int idx = tid + it * 256;
                int k = idx >> 4, c = idx & 15;
                int kk = k0 + k;
                int cin = kk / 9, rem = kk - cin * 9;
                int ky = rem / 3, kx = rem - ky * 3;
                const __half* src = &g_xh[s][kx][(size_t)(b * CIN + cin) * PLANE + ky * WPAD + p0 + c * 8];
                cp16(base + 49152u + (uint32_t)s * 16384u + (uint32_t)k * 256u + (uint32_t)((c ^ (k & 7)) << 4), src);
            }
        }
        CP_COMMIT();
    };

    load_stage(0, sbase);

    for (int kc = 0; kc < NKC; kc++) {
        const uint32_t cur = sbase + (uint32_t)(kc & 1) * BUFB;
        if (kc + 1 < NKC) {
            load_stage(kc + 1, sbase + (uint32_t)((kc + 1) & 1) * BUFB);
            CP_WAIT(1);
        } else {
            CP_WAIT(0);
        }
        __syncthreads();

        const uint32_t sA0 = cur, sA1 = cur + 16384u, sA2 = cur + 32768u;
        const uint32_t sB0 = cur + 49152u, sB1 = cur + 65536u, sB2 = cur + 81920u;
#pragma unroll
        for (int ks = 0; ks < 4; ks++) {
            uint32_t a0f[4][4], a1f[4][4], a2f[4][4], b0f[2][4], b1f[2][4], b2f[2][4];
#pragma unroll
            for (int mi = 0; mi < 4; mi++) {
                int m = warp_m + mi * 16 + m_lane;
                uint32_t off = (uint32_t)m * 128u + (uint32_t)(((ks * 2 + hi) ^ (m_lane & 7)) << 4);
                ldsm4(a0f[mi], sA0 + off);
                ldsm4(a1f[mi], sA1 + off);
                ldsm4(a2f[mi], sA2 + off);
            }
#pragma unroll
            for (int ni = 0; ni < 2; ni++) {
                int k = ks * 16 + m_lane;
                uint32_t off = (uint32_t)k * 256u + (uint32_t)(((nb + ni * 2 + hi) ^ (m_lane & 7)) << 4);
                ldsm4t(b0f[ni], sB0 + off);
                ldsm4t(b1f[ni], sB1 + off);
                ldsm4t(b2f[ni], sB2 + off);
            }
#pragma unroll
            for (int mi = 0; mi < 4; mi++)
#pragma unroll
                for (int g = 0; g < 4; g++) {
                    float* cc = C[mi][g];
                    const uint32_t* pb0 = &b0f[g >> 1][(g & 1) * 2];
                    const uint32_t* pb1 = &b1f[g >> 1][(g & 1) * 2];
                    const uint32_t* pb2 = &b2f[g >> 1][(g & 1) * 2];
                    mma16816(cc, a0f[mi], pb0);
                    mma16816(cc, a0f[mi], pb1);
                    mma16816(cc, a1f[mi], pb0);
                    mma16816(cc, a1f[mi], pb1);
                    mma16816(cc, a2f[mi], pb0);
                    mma16816(cc, a0f[mi], pb2);
                }
        }
#pragma unroll
        for (int mi = 0; mi < 4; mi++)
#pragma unroll
            for (int g = 0; g < 4; g++)
#pragma unroll
                for (int r = 0; r < 4; r++) {
                    S[mi][g][r] += C[mi][g][r];
                    C[mi][g][r] = 0.f;
                }
        __syncthreads();
    }

    float bz[4][2];
#pragma unroll
    for (int mi = 0; mi < 4; mi++)
#pragma unroll
        for (int h = 0; h < 2; h++)
            bz[mi][h] = bias[m0 + warp_m + mi * 16 + (lane >> 2) + 8 * h];

#pragma unroll
    for (int mi = 0; mi < 4; mi++)
#pragma unroll
        for (int g = 0; g < 4; g++)
#pragma unroll
            for (int r = 0; r < 4; r++) {
                int pp = p0 + warp_n + g * 8 + (lane & 3) * 2 + (r & 1);
                int y = pp / WPAD, x = pp - y * WPAD;
                if (x < 50 && y < 50) {
                    int m = m0 + warp_m + mi * 16 + (lane >> 2) + 8 * (r >> 1);
                    g_feat[((size_t)(b * HW + y * 50 + x) << 9) + m] =
                        fmaxf(S[mi][g][r] * UNSCALE + bz[mi][r >> 1], 0.f);
                }
            }
}

// ---------------- 1x1 heads: lane-per-pixel, warp-per-7-outputs ----------------
__global__ __launch_bounds__(256)
void heads_kernel(const float* __restrict__ lw, const float* __restrict__ lb,
                  const float* __restrict__ sw, const float* __restrict__ sb,
                  float* __restrict__ out) {
    extern __shared__ float4 ft4[];   // [128][33]: channel-quad x pixel
    const int b = blockIdx.y, p0 = blockIdx.x * 32, tid = threadIdx.x;
    const int lane = tid & 31, warp = tid >> 5;

    // transpose 32px x 512ch feature tile into SMEM
    for (int idx = tid; idx < 32 * 128; idx += 256) {
        int px = idx >> 7, cq = idx & 127;
        float4 v = make_float4(0.f, 0.f, 0.f, 0.f);
        if (p0 + px < HW)
            v = *(const float4*)&g_feat[((size_t)(b * HW + p0 + px) << 9) + cq * 4];
        ft4[cq * 33 + px] = v;
    }
    __syncthreads();

    const int o0 = warp * 7;   // 8 warps x 7 = 56 >= 54
    const float4* wrow[7];
    float bias7[7];
#pragma unroll
    for (int oi = 0; oi < 7; oi++) {
        int o = o0 + oi;
        if (o < 36)      { wrow[oi] = (const float4*)(lw + (o << 9));        bias7[oi] = lb[o]; }
        else if (o < 54) { wrow[oi] = (const float4*)(sw + ((o - 36) << 9)); bias7[oi] = sb[o - 36]; }
        else             { wrow[oi] = (const float4*)lw;                     bias7[oi] = 0.f; }
    }

    float acc[7] = {0.f, 0.f, 0.f, 0.f, 0.f, 0.f, 0.f};
    for (int cq = 0; cq < 128; cq++) {
        float4 f = ft4[cq * 33 + lane];
#pragma unroll
        for (int oi = 0; oi < 7; oi++) {
            float4 wv = __ldg(wrow[oi] + cq);
            acc[oi] += wv.x * f.x + wv.y * f.y + wv.z * f.z + wv.w * f.w;
        }
    }

    const int p = p0 + lane;
    if (p < HW) {
#pragma unroll
        for (int oi = 0; oi < 7; oi++) {
            int o = o0 + oi;
            if (o >= 54) break;
            float s = acc[oi] + bias7[oi];
            if (o < 36) {
                int a = o >> 2, j = o & 3;
                out[OFF_LOCS + b * (NANCH * 4) + (p * 9 + a) * 4 + j] = s;
            } else {
                int oo = o - 36, a = oo >> 1, j = oo & 1;
                out[OFF_SCORES + b * (NANCH * 2) + (p * 9 + a) * 2 + j] = s;
            }
        }
    }
}

// ---------------- anchors ----------------
__device__ __forceinline__ void anchor_of(int i, float& ax1, float& ay1, float& ax2, float& ay2) {
    int p = i / 9, a = i - p * 9;
    int y = p / 50, x = p - y * 50;
    int ri = a / 3, si = a - ri * 3;
    const double ratios[3] = {0.5, 1.0, 2.0};
    const double scales[3] = {8.0, 16.0, 32.0};
    double hh = 16.0 * scales[si] * sqrt(ratios[ri]);
    double ww = 16.0 * scales[si] * sqrt(1.0 / ratios[ri]);
    float sx = (float)(x * 16), sy = (float)(y * 16);
    ax1 = sx + (float)(8.0 - ww / 2.0); ay1 = sy + (float)(8.0 - hh / 2.0);
    ax2 = sx + (float)(8.0 + ww / 2.0); ay2 = sy + (float)(8.0 + hh / 2.0);
}
__global__ void anchor_kernel(float* __restrict__ out) {
    int i = blockIdx.x * blockDim.x + threadIdx.x;
    if (i >= NANCH) return;
    float a1, b1, a2, b2;
    anchor_of(i, a1, b1, a2, b2);
    out[OFF_ANCH + i * 4 + 0] = a1; out[OFF_ANCH + i * 4 + 1] = b1;
    out[OFF_ANCH + i * 4 + 2] = a2; out[OFF_ANCH + i * 4 + 3] = b2;
}

// ---------------- decode + keys ----------------
__device__ __forceinline__ float dim_to_float(const int* p) {
    int v = *p;
    if (v > 0 && v < 100000) return (float)v;
    return __int_as_float(v);
}
__global__ void decode_kernel(const float* __restrict__ out,
                              const int* __restrict__ imh, const int* __restrict__ imw) {
    const int b = blockIdx.y;
    const int i = blockIdx.x * blockDim.x + threadIdx.x;
    if (i >= PADN) return;
    unsigned long long key;
    if (i < NANCH) {
        float ax1, ay1, ax2, ay2;
        anchor_of(i, ax1, ay1, ax2, ay2);
        const float* loc = out + OFF_LOCS + b * (NANCH * 4) + i * 4;
        float aw = ax2 - ax1, ah = ay2 - ay1;
        float cx = loc[0] * aw + ax1 + 0.5f * aw;
        float cy = loc[1] * ah + ay1 + 0.5f * ah;
        float ww = expf(loc[2]) * aw, hh = expf(loc[3]) * ah;
        float Wf = dim_to_float(imw), Hf = dim_to_float(imh);
        float x1 = fminf(fmaxf(cx - 0.5f * ww, 0.f), Wf);
        float y1 = fminf(fmaxf(cy - 0.5f * hh, 0.f), Hf);
        float x2 = fminf(fmaxf(cx + 0.5f * ww, 0.f), Wf);
        float y2 = fminf(fmaxf(cy + 0.5f * hh, 0.f), Hf);
        bool valid = (x2 - x1 + 1.f >= 16.f) && (y2 - y1 + 1.f >= 16.f);
        float* bx = &g_boxes[((size_t)b * NANCH + i) * 4];
        bx[0] = x1; bx[1] = y1; bx[2] = x2; bx[3] = y2;
        g_valid[b * NANCH + i] = valid ? 1 : 0;
        const float* sc = out + OFF_SCORES + b * (NANCH * 2) + i * 2;
        float s0 = sc[0], s1 = sc[1];
        float m = fmaxf(s0, s1);
        float e0 = expf(s0 - m), e1 = expf(s1 - m);
        float fg = e1 / (e0 + e1);
        float score = valid ? fg : __int_as_float(0xFF800000);
        unsigned u = __float_as_uint(score);
        unsigned s = (u & 0x80000000u) ? ~u : (u | 0x80000000u);
        key = ((unsigned long long)(~s) << 32) | (unsigned)i;
    } else key = 0xFFFFFFFFFFFFFFFFull;
    g_keys[(size_t)b * PADN + i] = key;
}

// ---------------- per-chunk bitonic sort ----------------
__global__ __launch_bounds__(512)
void sort_kernel() {
    __shared__ unsigned long long sk[CHUNK];
    const int c = blockIdx.x % NCHUNK, b = blockIdx.x / NCHUNK;
    unsigned long long* gk = g_keys + (size_t)b * PADN + c * CHUNK;
    for (int i = threadIdx.x; i < CHUNK; i += 512) sk[i] = gk[i];
    __syncthreads();
    for (int k = 2; k <= CHUNK; k <<= 1)
        for (int j = k >> 1; j > 0; j >>= 1) {
            for (int t = threadIdx.x; t < CHUNK; t += 512) {
                int l = t ^ j;
                if (l > t) {
                    bool up = ((t & k) == 0);
                    unsigned long long a = sk[t], bv = sk[l];
                    if ((a > bv) == up) { sk[t] = bv; sk[l] = a; }
                }
            }
            __syncthreads();
        }
    for (int i = threadIdx.x; i < CHUNK; i += 512) gk[i] = sk[i];
}

// ---------------- co-rank merge -> exact top-3000 ----------------
__global__ void merge_kernel() {
    const int b = blockIdx.y;
    const int t = blockIdx.x * blockDim.x + threadIdx.x;
    if (t >= NCHUNK * NPRE) return;
    const int c = t / NPRE, i = t - c * NPRE;
    const unsigned long long* base = g_keys + (size_t)b * PADN;
    unsigned long long key = base[c * CHUNK + i];
    if ((unsigned)(key >> 32) == 0xFFFFFFFFu) return;
    int rank = i;
#pragma unroll
    for (int cc = 0; cc < NCHUNK; cc++) {
        if (cc == c) continue;
        const unsigned long long* arr = base + cc * CHUNK;
        int pos = 0;
#pragma unroll
        for (int s = CHUNK / 2; s > 0; s >>= 1)
            if (arr[pos + s - 1] < key) pos += s;
        rank += pos;
    }
    if (rank < NPRE) {
        int idx = (int)(key & 0xFFFFFFFFull);
        int o = b * NPRE + rank;
        ((float4*)g_sboxes)[o] = *(const float4*)&g_boxes[((size_t)b * NANCH + idx) * 4];
        g_svalid[o] = g_valid[b * NANCH + idx];
    }
}

// ---------------- NMS: suppression bitmatrix ----------------
__global__ __launch_bounds__(1024)
void nms_build_kernel() {
    __shared__ float4 bx[NPRE];
    const int b = blockIdx.y, tid = threadIdx.x;
    const int lane = tid & 31, warp = tid >> 5;
    for (int idx = tid; idx < NPRE; idx += 1024)
        bx[idx] = ((const float4*)g_sboxes)[b * NPRE + idx];
    __syncthreads();
    int i = blockIdx.x * 32 + warp;
    if (i >= NPRE) return;
    float4 bi = bx[i];
    float ai = (bi.z - bi.x) * (bi.w - bi.y);
    for (int jw = 0; jw < 94; jw++) {
        int j = jw * 32 + lane;
        bool sup = false;
        if (j < NPRE && j > i) {
            float4 bj = bx[j];
            float iw = fmaxf(fminf(bi.z, bj.z) - fmaxf(bi.x, bj.x), 0.f);
            float ih = fmaxf(fminf(bi.w, bj.w) - fmaxf(bi.y, bj.y), 0.f);
            float inter = iw * ih;
            float aj = (bj.z - bj.x) * (bj.w - bj.y);
            sup = inter / (ai + aj - inter + 1e-9f) > 0.7f;
        }
        unsigned word = __ballot_sync(0xFFFFFFFFu, sup);
        if (lane == 0) g_sup[b][i][jw] = word;
    }
    if (lane < 2) g_sup[b][i][94 + lane] = 0;
}

// ---------------- NMS: single-warp greedy scan + output ----------------
#define STILE 64
__global__ __launch_bounds__(256)
void nms_scan_kernel(float* __restrict__ out) {
    extern __shared__ unsigned srows[];
    __shared__ unsigned keepw[96];
    const int b = blockIdx.x, tid = threadIdx.x;
    const int lane = tid & 31, warp = tid >> 5;

    for (int w = tid; w < 96; w += 256) {
        unsigned word = 0;
        for (int q = 0; q < 32; q++) {
            int idx = w * 32 + q;
            if (idx < NPRE && g_svalid[b * NPRE + idx]) word |= (1u << q);
        }
        keepw[w] = word;
    }
    for (int idx = tid; idx < STILE * 24; idx += 256) {
        int i = idx / 24, w4 = idx % 24;
        uint4 v = make_uint4(0, 0, 0, 0);
        if (i < NPRE) v = ((const uint4*)g_sup[b][i])[w4];
        ((uint4*)srows)[idx] = v;
    }
    __syncthreads();

    const int ntiles = (NPRE + STILE - 1) / STILE;
    for (int t = 0; t < ntiles; t++) {
        if (warp > 0 && t + 1 < ntiles) {
            unsigned* buf = srows + ((t + 1) & 1) * STILE * 96;
            for (int idx = tid - 32; idx < STILE * 24; idx += 224) {
                int i = (t + 1) * STILE + idx / 24, w4 = idx % 24;
                uint4 v = make_uint4(0, 0, 0, 0);
                if (i < NPRE) v = ((const uint4*)g_sup[b][i])[w4];
                ((uint4*)buf)[idx] = v;
            }
        }
        if (warp == 0) {
            const unsigned* buf = srows + (t & 1) * STILE * 96;
            unsigned wcur = 0;
            for (int ii = 0; ii < STILE; ii++) {
                int i = t * STILE + ii;
                if (i >= NPRE) break;
                int cw = i >> 5, bit = i & 31;
                if (bit == 0) { __syncwarp(); wcur = keepw[cw]; }
                if ((wcur >> bit) & 1) {
                    const unsigned* row = buf + ii * 96;
                    wcur &= ~row[cw];
                    keepw[lane]      &= ~row[lane];
                    keepw[lane + 32] &= ~row[lane + 32];
                    keepw[lane + 64] &= ~row[lane + 64];
                }
            }
        }
        __syncthreads();
    }

    for (int q = tid; q < NPOST * 4; q += 256) out[OFF_ROIS + b * (NPOST * 4) + q] = 0.f;
    for (int q = tid; q < NPOST; q += 256) out[OFF_RIDX + b * NPOST + q] = (float)b;
    __syncthreads();

    if (warp == 0) {
        int cnt = 0;
        for (int w0 = 0; w0 < 94; w0++) {
            unsigned flags = keepw[w0];
            int j = w0 * 32 + lane;
            bool f = (flags >> lane) & 1;
            int pos = cnt + __popc(flags & ((1u << lane) - 1u));
            if (f && pos < NPOST && j < NPRE) {
                float4 bb = ((const float4*)g_sboxes)[b * NPRE + j];
                float* o = out + OFF_ROIS + b * (NPOST * 4) + pos * 4;
                o[0] = bb.x; o[1] = bb.y; o[2] = bb.z; o[3] = bb.w;
            }
            cnt += __popc(flags);
            if (cnt >= NPOST) break;
        }
    }
}

// ---------------- launcher ----------------
extern "C" void kernel_launch(void* const* d_in, const int* in_sizes, int n_in,
                              void* d_out, int out_size) {
    const float* x  = (const float*)d_in[0];
    const float* w1 = (const float*)d_in[1];
    const float* b1 = (const float*)d_in[2];
    const float* lw = (const float*)d_in[3];
    const float* lb = (const float*)d_in[4];
    const float* sw = (const float*)d_in[5];
    const float* sb = (const float*)d_in[6];
    const int* ih   = (const int*)d_in[7];
    const int* iw   = (const int*)d_in[8];
    float* out = (float*)d_out;

    cudaFuncSetAttribute(conv_mma_kernel, cudaFuncAttributeMaxDynamicSharedMemorySize, CONV_SMEM);
    cudaFuncSetAttribute(heads_kernel, cudaFuncAttributeMaxDynamicSharedMemorySize, HEADS_SMEM);
    cudaFuncSetAttribute(nms_scan_kernel, cudaFuncAttributeMaxDynamicSharedMemorySize, 2 * STILE * 96 * 4);

    split_x_kernel<<<NB * CIN, 256>>>(x);
    split_w_kernel<<<(COUT * KDIM + 255) / 256, 256>>>(w1);
    conv_mma_kernel<<<dim3(NTILES_N, 4, NB), 256, CONV_SMEM>>>(b1);
    heads_kernel<<<dim3((HW + 31) / 32, NB), 256, HEADS_SMEM>>>(lw, lb, sw, sb, out);
    anchor_kernel<<<(NANCH + 255) / 256, 256>>>(out);
    decode_kernel<<<dim3((PADN + 255) / 256, NB), 256>>>(out, ih, iw);
    sort_kernel<<<NB * NCHUNK, 512>>>();
    merge_kernel<<<dim3((NCHUNK * NPRE + 255) / 256, NB), 256>>>();
    nms_build_kernel<<<dim3((NPRE + 31) / 32, NB), 1024>>>();
    nms_scan_kernel<<<NB, 256, 2 * STILE * 96 * 4>>>(out);
}

// round 8
// speedup vs baseline: 4.6210x; 1.4529x over previous
#include <cuda_runtime.h>
#include <cuda_fp16.h>
#include <math.h>
#include <stdint.h>

#define NB 4
#define HW 2500
#define CIN 512
#define COUT 512
#define KDIM 4608
#define NANCH 22500
#define NPRE 3000
#define NPOST 300
#define NCHUNK 6
#define CHUNK 4096
#define PADN (NCHUNK*CHUNK)

#define OFF_LOCS 0
#define OFF_SCORES (NB*NANCH*4)
#define OFF_ROIS (OFF_SCORES+NB*NANCH*2)
#define OFF_RIDX (OFF_ROIS+NB*NPOST*4)
#define OFF_ANCH (OFF_RIDX+NB*NPOST)

#define WPAD 56
#define PLANE 3072
#define KC 64
#define NKC 72
#define NTILES_N 22
#define BUFB 65536u
#define CONV_SMEM (2*65536)
#define XSCALE 256.0f
#define WSCALE 64.0f
#define UNSCALE (1.0f/16384.0f)
#define HEADS_SMEM (128*33*16)

// ---------------- scratch ----------------
__device__ __align__(16) __half g_xh[2][3][(size_t)NB*CIN*PLANE];
__device__ __align__(16) __half g_wh[2][(size_t)COUT*KDIM];
__device__ float g_feat[(size_t)NB*HW*COUT];
__device__ float g_boxes[NB*NANCH*4];
__device__ unsigned char g_valid[NB*NANCH];
__device__ unsigned long long g_keys[NB*PADN];
__device__ float g_sboxes[NB*NPRE*4];
__device__ unsigned char g_svalid[NB*NPRE];
__device__ unsigned g_sup[NB][3008][96];

// ---------------- PTX helpers ----------------
__device__ __forceinline__ uint32_t smem_u32(const void* p) {
    uint32_t a;
    asm("{ .reg .u64 t; cvta.to.shared.u64 t, %1; cvt.u32.u64 %0, t; }" : "=r"(a) : "l"(p));
    return a;
}
__device__ __forceinline__ void cp16(uint32_t dst, const void* src) {
    asm volatile("cp.async.cg.shared.global [%0], [%1], 16;" :: "r"(dst), "l"(src) : "memory");
}
#define CP_COMMIT() asm volatile("cp.async.commit_group;" ::: "memory")
#define CP_WAIT(n)  asm volatile("cp.async.wait_group %0;" :: "n"(n) : "memory")

__device__ __forceinline__ void ldsm4(uint32_t* r, uint32_t a) {
    asm volatile("ldmatrix.sync.aligned.m8n8.x4.shared.b16 {%0,%1,%2,%3}, [%4];"
        : "=r"(r[0]), "=r"(r[1]), "=r"(r[2]), "=r"(r[3]) : "r"(a));
}
__device__ __forceinline__ void ldsm4t(uint32_t* r, uint32_t a) {
    asm volatile("ldmatrix.sync.aligned.m8n8.x4.trans.shared.b16 {%0,%1,%2,%3}, [%4];"
        : "=r"(r[0]), "=r"(r[1]), "=r"(r[2]), "=r"(r[3]) : "r"(a));
}
__device__ __forceinline__ void mma16816(float* c, const uint32_t* a, const uint32_t* b) {
    asm volatile("mma.sync.aligned.m16n8k16.row.col.f32.f16.f16.f32 "
        "{%0,%1,%2,%3}, {%4,%5,%6,%7}, {%8,%9}, {%0,%1,%2,%3};"
        : "+f"(c[0]), "+f"(c[1]), "+f"(c[2]), "+f"(c[3])
        : "r"(a[0]), "r"(a[1]), "r"(a[2]), "r"(a[3]), "r"(b[0]), "r"(b[1]));
}

// ---------------- splits (scaled 2-term fp16) ----------------
__global__ void split_x_kernel(const float* __restrict__ X) {
    const int bc = blockIdx.x;
    const float* src = X + (size_t)bc * HW;
    for (int idx = threadIdx.x; idx < PLANE; idx += 256) {
        int yy = idx / WPAD, xx = idx - yy * WPAD;
        int iy = yy - 1;
#pragma unroll
        for (int kx = 0; kx < 3; kx++) {
            int ix = xx + kx - 1;
            float v = 0.f;
            if (iy >= 0 && iy < 50 && ix >= 0 && ix < 50) v = src[iy * 50 + ix];
            v *= XSCALE;
            __half h0 = __float2half(v);
            __half h1 = __float2half(v - __half2float(h0));
            size_t o = (size_t)bc * PLANE + idx;
            g_xh[0][kx][o] = h0; g_xh[1][kx][o] = h1;
        }
    }
}
__global__ void split_w_kernel(const float* __restrict__ W) {
    int i = blockIdx.x * 256 + threadIdx.x;
    if (i >= COUT * KDIM) return;
    float v = W[i] * WSCALE;
    __half h0 = __float2half(v);
    g_wh[0][i] = h0;
    g_wh[1][i] = __float2half(v - __half2float(h0));
}

// ---------------- conv 3x3 via mma.sync: 2-term split, 3 products, per-chunk flush ----
__global__ __launch_bounds__(256, 1)
void conv_mma_kernel(const float* __restrict__ bias) {
    extern __shared__ char dsm[];
    const uint32_t sbase = smem_u32(dsm);
    const int tid = threadIdx.x;
    const int lane = tid & 31, warp = tid >> 5;
    const int p0 = blockIdx.x * 128;
    const int m0 = blockIdx.y * 128;
    const int b  = blockIdx.z;
    const int warp_m = (warp >> 2) * 64;
    const int warp_n = (warp & 3) * 32;

    float C[4][4][4];
    float S[4][4][4];
#pragma unroll
    for (int i = 0; i < 4; i++)
#pragma unroll
        for (int j = 0; j < 4; j++)
#pragma unroll
            for (int r = 0; r < 4; r++) { C[i][j][r] = 0.f; S[i][j][r] = 0.f; }

    const int m_lane = lane & 15, hi = lane >> 4;
    const int nb = warp_n >> 3;

    auto load_stage = [&](int kc, uint32_t base) {
        const int k0 = kc * KC;
#pragma unroll
        for (int s = 0; s < 2; s++) {
            const __half* wsrc = g_wh[s];
#pragma unroll
            for (int it = 0; it < 4; it++) {
                int idx = tid + it * 256;
                int m = idx >> 3, c = idx & 7;
                cp16(base + (uint32_t)s * 16384u + (uint32_t)m * 128u + (uint32_t)((c ^ (m & 7)) << 4),
                     wsrc + (size_t)(m0 + m) * KDIM + k0 + c * 8);
            }
#pragma unroll
            for (int it = 0; it < 4; it++) {
                int idx = tid + it * 256;
                int k = idx >> 4, c = idx & 15;
                int kk = k0 + k;
                int cin = kk / 9, rem = kk - cin * 9;
                int ky = rem / 3, kx = rem - ky * 3;
                const __half* src = &g_xh[s][kx][(size_t)(b * CIN + cin) * PLANE + ky * WPAD + p0 + c * 8];
                cp16(base + 32768u + (uint32_t)s * 16384u + (uint32_t)k * 256u + (uint32_t)((c ^ (k & 7)) << 4), src);
            }
        }
        CP_COMMIT();
    };

    load_stage(0, sbase);

    for (int kc = 0; kc < NKC; kc++) {
        const uint32_t cur = sbase + (uint32_t)(kc & 1) * BUFB;
        if (kc + 1 < NKC) {
            load_stage(kc + 1, sbase + (uint32_t)((kc + 1) & 1) * BUFB);
            CP_WAIT(1);
        } else {
            CP_WAIT(0);
        }
        __syncthreads();

        const uint32_t sA0 = cur, sA1 = cur + 16384u;
        const uint32_t sB0 = cur + 32768u, sB1 = cur + 49152u;
#pragma unroll
        for (int ks = 0; ks < 4; ks++) {
            uint32_t a0f[4][4], a1f[4][4], b0f[2][4], b1f[2][4];
#pragma unroll
            for (int mi = 0; mi < 4; mi++) {
                int m = warp_m + mi * 16 + m_lane;
                uint32_t off = (uint32_t)m * 128u + (uint32_t)(((ks * 2 + hi) ^ (m_lane & 7)) << 4);
                ldsm4(a0f[mi], sA0 + off);
                ldsm4(a1f[mi], sA1 + off);
            }
#pragma unroll
            for (int ni = 0; ni < 2; ni++) {
                int k = ks * 16 + m_lane;
                uint32_t off = (uint32_t)k * 256u + (uint32_t)(((nb + ni * 2 + hi) ^ (m_lane & 7)) << 4);
                ldsm4t(b0f[ni], sB0 + off);
                ldsm4t(b1f[ni], sB1 + off);
            }
#pragma unroll
            for (int mi = 0; mi < 4; mi++)
#pragma unroll
                for (int g = 0; g < 4; g++) {
                    float* cc = C[mi][g];
                    const uint32_t* pb0 = &b0f[g >> 1][(g & 1) * 2];
                    const uint32_t* pb1 = &b1f[g >> 1][(g & 1) * 2];
                    mma16816(cc, a0f[mi], pb0);
                    mma16816(cc, a0f[mi], pb1);
                    mma16816(cc, a1f[mi], pb0);
                }
        }
#pragma unroll
        for (int mi = 0; mi < 4; mi++)
#pragma unroll
            for (int g = 0; g < 4; g++)
#pragma unroll
                for (int r = 0; r < 4; r++) {
                    S[mi][g][r] += C[mi][g][r];
                    C[mi][g][r] = 0.f;
                }
        __syncthreads();
    }

    float bz[4][2];
#pragma unroll
    for (int mi = 0; mi < 4; mi++)
#pragma unroll
        for (int h = 0; h < 2; h++)
            bz[mi][h] = bias[m0 + warp_m + mi * 16 + (lane >> 2) + 8 * h];

#pragma unroll
    for (int mi = 0; mi < 4; mi++)
#pragma unroll
        for (int g = 0; g < 4; g++)
#pragma unroll
            for (int r = 0; r < 4; r++) {
                int pp = p0 + warp_n + g * 8 + (lane & 3) * 2 + (r & 1);
                int y = pp / WPAD, x = pp - y * WPAD;
                if (x < 50 && y < 50) {
                    int m = m0 + warp_m + mi * 16 + (lane >> 2) + 8 * (r >> 1);
                    g_feat[((size_t)(b * HW + y * 50 + x) << 9) + m] =
                        fmaxf(S[mi][g][r] * UNSCALE + bz[mi][r >> 1], 0.f);
                }
            }
}

// ---------------- 1x1 heads: lane-per-pixel, warp-per-7-outputs ----------------
__global__ __launch_bounds__(256)
void heads_kernel(const float* __restrict__ lw, const float* __restrict__ lb,
                  const float* __restrict__ sw, const float* __restrict__ sb,
                  float* __restrict__ out) {
    extern __shared__ float4 ft4[];
    const int b = blockIdx.y, p0 = blockIdx.x * 32, tid = threadIdx.x;
    const int lane = tid & 31, warp = tid >> 5;

    for (int idx = tid; idx < 32 * 128; idx += 256) {
        int px = idx >> 7, cq = idx & 127;
        float4 v = make_float4(0.f, 0.f, 0.f, 0.f);
        if (p0 + px < HW)
            v = *(const float4*)&g_feat[((size_t)(b * HW + p0 + px) << 9) + cq * 4];
        ft4[cq * 33 + px] = v;
    }
    __syncthreads();

    const int o0 = warp * 7;
    const float4* wrow[7];
    float bias7[7];
#pragma unroll
    for (int oi = 0; oi < 7; oi++) {
        int o = o0 + oi;
        if (o < 36)      { wrow[oi] = (const float4*)(lw + (o << 9));        bias7[oi] = lb[o]; }
        else if (o < 54) { wrow[oi] = (const float4*)(sw + ((o - 36) << 9)); bias7[oi] = sb[o - 36]; }
        else             { wrow[oi] = (const float4*)lw;                     bias7[oi] = 0.f; }
    }

    float acc[7] = {0.f, 0.f, 0.f, 0.f, 0.f, 0.f, 0.f};
    for (int cq = 0; cq < 128; cq++) {
        float4 f = ft4[cq * 33 + lane];
#pragma unroll
        for (int oi = 0; oi < 7; oi++) {
            float4 wv = __ldg(wrow[oi] + cq);
            acc[oi] += wv.x * f.x + wv.y * f.y + wv.z * f.z + wv.w * f.w;
        }
    }

    const int p = p0 + lane;
    if (p < HW) {
#pragma unroll
        for (int oi = 0; oi < 7; oi++) {
            int o = o0 + oi;
            if (o >= 54) break;
            float s = acc[oi] + bias7[oi];
            if (o < 36) {
                int a = o >> 2, j = o & 3;
                out[OFF_LOCS + b * (NANCH * 4) + (p * 9 + a) * 4 + j] = s;
            } else {
                int oo = o - 36, a = oo >> 1, j = oo & 1;
                out[OFF_SCORES + b * (NANCH * 2) + (p * 9 + a) * 2 + j] = s;
            }
        }
    }
}

// ---------------- anchors ----------------
__device__ __forceinline__ void anchor_of(int i, float& ax1, float& ay1, float& ax2, float& ay2) {
    int p = i / 9, a = i - p * 9;
    int y = p / 50, x = p - y * 50;
    int ri = a / 3, si = a - ri * 3;
    const double ratios[3] = {0.5, 1.0, 2.0};
    const double scales[3] = {8.0, 16.0, 32.0};
    double hh = 16.0 * scales[si] * sqrt(ratios[ri]);
    double ww = 16.0 * scales[si] * sqrt(1.0 / ratios[ri]);
    float sx = (float)(x * 16), sy = (float)(y * 16);
    ax1 = sx + (float)(8.0 - ww / 2.0); ay1 = sy + (float)(8.0 - hh / 2.0);
    ax2 = sx + (float)(8.0 + ww / 2.0); ay2 = sy + (float)(8.0 + hh / 2.0);
}
__global__ void anchor_kernel(float* __restrict__ out) {
    int i = blockIdx.x * blockDim.x + threadIdx.x;
    if (i >= NANCH) return;
    float a1, b1, a2, b2;
    anchor_of(i, a1, b1, a2, b2);
    out[OFF_ANCH + i * 4 + 0] = a1; out[OFF_ANCH + i * 4 + 1] = b1;
    out[OFF_ANCH + i * 4 + 2] = a2; out[OFF_ANCH + i * 4 + 3] = b2;
}

// ---------------- decode + keys ----------------
__device__ __forceinline__ float dim_to_float(const int* p) {
    int v = *p;
    if (v > 0 && v < 100000) return (float)v;
    return __int_as_float(v);
}
__global__ void decode_kernel(const float* __restrict__ out,
                              const int* __restrict__ imh, const int* __restrict__ imw) {
    const int b = blockIdx.y;
    const int i = blockIdx.x * blockDim.x + threadIdx.x;
    if (i >= PADN) return;
    unsigned long long key;
    if (i < NANCH) {
        float ax1, ay1, ax2, ay2;
        anchor_of(i, ax1, ay1, ax2, ay2);
        const float* loc = out + OFF_LOCS + b * (NANCH * 4) + i * 4;
        float aw = ax2 - ax1, ah = ay2 - ay1;
        float cx = loc[0] * aw + ax1 + 0.5f * aw;
        float cy = loc[1] * ah + ay1 + 0.5f * ah;
        float ww = expf(loc[2]) * aw, hh = expf(loc[3]) * ah;
        float Wf = dim_to_float(imw), Hf = dim_to_float(imh);
        float x1 = fminf(fmaxf(cx - 0.5f * ww, 0.f), Wf);
        float y1 = fminf(fmaxf(cy - 0.5f * hh, 0.f), Hf);
        float x2 = fminf(fmaxf(cx + 0.5f * ww, 0.f), Wf);
        float y2 = fminf(fmaxf(cy + 0.5f * hh, 0.f), Hf);
        bool valid = (x2 - x1 + 1.f >= 16.f) && (y2 - y1 + 1.f >= 16.f);
        float* bx = &g_boxes[((size_t)b * NANCH + i) * 4];
        bx[0] = x1; bx[1] = y1; bx[2] = x2; bx[3] = y2;
        g_valid[b * NANCH + i] = valid ? 1 : 0;
        const float* sc = out + OFF_SCORES + b * (NANCH * 2) + i * 2;
        float s0 = sc[0], s1 = sc[1];
        float m = fmaxf(s0, s1);
        float e0 = expf(s0 - m), e1 = expf(s1 - m);
        float fg = e1 / (e0 + e1);
        float score = valid ? fg : __int_as_float(0xFF800000);
        unsigned u = __float_as_uint(score);
        unsigned s = (u & 0x80000000u) ? ~u : (u | 0x80000000u);
        key = ((unsigned long long)(~s) << 32) | (unsigned)i;
    } else key = 0xFFFFFFFFFFFFFFFFull;
    g_keys[(size_t)b * PADN + i] = key;
}

// ---------------- per-chunk bitonic sort ----------------
__global__ __launch_bounds__(512)
void sort_kernel() {
    __shared__ unsigned long long sk[CHUNK];
    const int c = blockIdx.x % NCHUNK, b = blockIdx.x / NCHUNK;
    unsigned long long* gk = g_keys + (size_t)b * PADN + c * CHUNK;
    for (int i = threadIdx.x; i < CHUNK; i += 512) sk[i] = gk[i];
    __syncthreads();
    for (int k = 2; k <= CHUNK; k <<= 1)
        for (int j = k >> 1; j > 0; j >>= 1) {
            for (int t = threadIdx.x; t < CHUNK; t += 512) {
                int l = t ^ j;
                if (l > t) {
                    bool up = ((t & k) == 0);
                    unsigned long long a = sk[t], bv = sk[l];
                    if ((a > bv) == up) { sk[t] = bv; sk[l] = a; }
                }
            }
            __syncthreads();
        }
    for (int i = threadIdx.x; i < CHUNK; i += 512) gk[i] = sk[i];
}

// ---------------- co-rank merge -> exact top-3000 ----------------
__global__ void merge_kernel() {
    const int b = blockIdx.y;
    const int t = blockIdx.x * blockDim.x + threadIdx.x;
    if (t >= NCHUNK * NPRE) return;
    const int c = t / NPRE, i = t - c * NPRE;
    const unsigned long long* base = g_keys + (size_t)b * PADN;
    unsigned long long key = base[c * CHUNK + i];
    if ((unsigned)(key >> 32) == 0xFFFFFFFFu) return;
    int rank = i;
#pragma unroll
    for (int cc = 0; cc < NCHUNK; cc++) {
        if (cc == c) continue;
        const unsigned long long* arr = base + cc * CHUNK;
        int pos = 0;
#pragma unroll
        for (int s = CHUNK / 2; s > 0; s >>= 1)
            if (arr[pos + s - 1] < key) pos += s;
        rank += pos;
    }
    if (rank < NPRE) {
        int idx = (int)(key & 0xFFFFFFFFull);
        int o = b * NPRE + rank;
        ((float4*)g_sboxes)[o] = *(const float4*)&g_boxes[((size_t)b * NANCH + idx) * 4];
        g_svalid[o] = g_valid[b * NANCH + idx];
    }
}

// ---------------- NMS: suppression bitmatrix ----------------
__global__ __launch_bounds__(1024)
void nms_build_kernel() {
    __shared__ float4 bx[NPRE];
    const int b = blockIdx.y, tid = threadIdx.x;
    const int lane = tid & 31, warp = tid >> 5;
    for (int idx = tid; idx < NPRE; idx += 1024)
        bx[idx] = ((const float4*)g_sboxes)[b * NPRE + idx];
    __syncthreads();
    int i = blockIdx.x * 32 + warp;
    if (i >= NPRE) return;
    float4 bi = bx[i];
    float ai = (bi.z - bi.x) * (bi.w - bi.y);
    for (int jw = 0; jw < 94; jw++) {
        int j = jw * 32 + lane;
        bool sup = false;
        if (j < NPRE && j > i) {
            float4 bj = bx[j];
            float iw = fmaxf(fminf(bi.z, bj.z) - fmaxf(bi.x, bj.x), 0.f);
            float ih = fmaxf(fminf(bi.w, bj.w) - fmaxf(bi.y, bj.y), 0.f);
            float inter = iw * ih;
            float aj = (bj.z - bj.x) * (bj.w - bj.y);
            sup = inter / (ai + aj - inter + 1e-9f) > 0.7f;
        }
        unsigned word = __ballot_sync(0xFFFFFFFFu, sup);
        if (lane == 0) g_sup[b][i][jw] = word;
    }
    if (lane < 2) g_sup[b][i][94 + lane] = 0;
}

// ---------------- NMS: single-warp greedy scan + output ----------------
#define STILE 64
__global__ __launch_bounds__(256)
void nms_scan_kernel(float* __restrict__ out) {
    extern __shared__ unsigned srows[];
    __shared__ unsigned keepw[96];
    const int b = blockIdx.x, tid = threadIdx.x;
    const int lane = tid & 31, warp = tid >> 5;

    for (int w = tid; w < 96; w += 256) {
        unsigned word = 0;
        for (int q = 0; q < 32; q++) {
            int idx = w * 32 + q;
            if (idx < NPRE && g_svalid[b * NPRE + idx]) word |= (1u << q);
        }
        keepw[w] = word;
    }
    for (int idx = tid; idx < STILE * 24; idx += 256) {
        int i = idx / 24, w4 = idx % 24;
        uint4 v = make_uint4(0, 0, 0, 0);
        if (i < NPRE) v = ((const uint4*)g_sup[b][i])[w4];
        ((uint4*)srows)[idx] = v;
    }
    __syncthreads();

    const int ntiles = (NPRE + STILE - 1) / STILE;
    for (int t = 0; t < ntiles; t++) {
        if (warp > 0 && t + 1 < ntiles) {
            unsigned* buf = srows + ((t + 1) & 1) * STILE * 96;
            for (int idx = tid - 32; idx < STILE * 24; idx += 224) {
                int i = (t + 1) * STILE + idx / 24, w4 = idx % 24;
                uint4 v = make_uint4(0, 0, 0, 0);
                if (i < NPRE) v = ((const uint4*)g_sup[b][i])[w4];
                ((uint4*)buf)[idx] = v;
            }
        }
        if (warp == 0) {
            const unsigned* buf = srows + (t & 1) * STILE * 96;
            unsigned wcur = 0;
            for (int ii = 0; ii < STILE; ii++) {
                int i = t * STILE + ii;
                if (i >= NPRE) break;
                int cw = i >> 5, bit = i & 31;
                if (bit == 0) { __syncwarp(); wcur = keepw[cw]; }
                if ((wcur >> bit) & 1) {
                    const unsigned* row = buf + ii * 96;
                    wcur &= ~row[cw];
                    keepw[lane]      &= ~row[lane];
                    keepw[lane + 32] &= ~row[lane + 32];
                    keepw[lane + 64] &= ~row[lane + 64];
                }
            }
        }
        __syncthreads();
    }

    for (int q = tid; q < NPOST * 4; q += 256) out[OFF_ROIS + b * (NPOST * 4) + q] = 0.f;
    for (int q = tid; q < NPOST; q += 256) out[OFF_RIDX + b * NPOST + q] = (float)b;
    __syncthreads();

    if (warp == 0) {
        int cnt = 0;
        for (int w0 = 0; w0 < 94; w0++) {
            unsigned flags = keepw[w0];
            int j = w0 * 32 + lane;
            bool f = (flags >> lane) & 1;
            int pos = cnt + __popc(flags & ((1u << lane) - 1u));
            if (f && pos < NPOST && j < NPRE) {
                float4 bb = ((const float4*)g_sboxes)[b * NPRE + j];
                float* o = out + OFF_ROIS + b * (NPOST * 4) + pos * 4;
                o[0] = bb.x; o[1] = bb.y; o[2] = bb.z; o[3] = bb.w;
            }
            cnt += __popc(flags);
            if (cnt >= NPOST) break;
        }
    }
}

// ---------------- launcher ----------------
extern "C" void kernel_launch(void* const* d_in, const int* in_sizes, int n_in,
                              void* d_out, int out_size) {
    const float* x  = (const float*)d_in[0];
    const float* w1 = (const float*)d_in[1];
    const float* b1 = (const float*)d_in[2];
    const float* lw = (const float*)d_in[3];
    const float* lb = (const float*)d_in[4];
    const float* sw = (const float*)d_in[5];
    const float* sb = (const float*)d_in[6];
    const int* ih   = (const int*)d_in[7];
    const int* iw   = (const int*)d_in[8];
    float* out = (float*)d_out;

    cudaFuncSetAttribute(conv_mma_kernel, cudaFuncAttributeMaxDynamicSharedMemorySize, CONV_SMEM);
    cudaFuncSetAttribute(heads_kernel, cudaFuncAttributeMaxDynamicSharedMemorySize, HEADS_SMEM);
    cudaFuncSetAttribute(nms_scan_kernel, cudaFuncAttributeMaxDynamicSharedMemorySize, 2 * STILE * 96 * 4);

    split_x_kernel<<<NB * CIN, 256>>>(x);
    split_w_kernel<<<(COUT * KDIM + 255) / 256, 256>>>(w1);
    conv_mma_kernel<<<dim3(NTILES_N, 4, NB), 256, CONV_SMEM>>>(b1);
    heads_kernel<<<dim3((HW + 31) / 32, NB), 256, HEADS_SMEM>>>(lw, lb, sw, sb, out);
    anchor_kernel<<<(NANCH + 255) / 256, 256>>>(out);
    decode_kernel<<<dim3((PADN + 255) / 256, NB), 256>>>(out, ih, iw);
    sort_kernel<<<NB * NCHUNK, 512>>>();
    merge_kernel<<<dim3((NCHUNK * NPRE + 255) / 256, NB), 256>>>();
    nms_build_kernel<<<dim3((NPRE + 31) / 32, NB), 1024>>>();
    nms_scan_kernel<<<NB, 256, 2 * STILE * 96 * 4>>>(out);
}